// round 13
// baseline (speedup 1.0000x reference)
#include <cuda_runtime.h>
#include <cuda_fp16.h>
#include <math.h>
#include <stdint.h>

#define BB    1024
#define DIMC  512
#define D2C   1024
#define HIDC  2048
#define NBASE 30
#define KBIG  (NBASE * D2C)     // 30720
#define KBIG2 (KBIG + 1024)     // 31744 (incl. bias block r=30)
#define G1Z   4

#define PI_F      3.14159265358979323846f
#define INV_EMB   36.3636363636363636f
#define LN_EPS_F  1e-5f

__device__ __half g_atth[BB * 32];          // 0..29 att, 30 = 1.0, 31 = 0
__device__ __half g_eh2[BB * 2048];         // [0:1024) e, [1024:1056) att, rest 0
__device__ __half g_hin[BB * D2C];
__device__ __half g_WT[(size_t)D2C * KBIG2];
__device__ float  g_rt[(size_t)G1Z * BB * D2C];
__device__ __half g_h1[BB * HIDC];
__device__ __half g_h2[BB * HIDC];
__device__ float  g_x0[2 * BB * D2C];
__device__ __half g_xstack[2 * BB * D2C];
__device__ __half g_a[2 * BB * DIMC];
__device__ __half g_w1h[HIDC * D2C];
__device__ __half g_w2h[HIDC * HIDC];
__device__ __half g_w0h[D2C * HIDC];
__device__ __half g_wa1h[DIMC * D2C];
__device__ __half g_wa2h[D2C * DIMC];

__device__ __forceinline__ uint32_t smem_u32(const void* p) {
    uint32_t a;
    asm("{ .reg .u64 t; cvta.to.shared.u64 t, %1; cvt.u32.u64 %0, t; }" : "=r"(a) : "l"(p));
    return a;
}
__device__ __forceinline__ void cp16(uint32_t d, const void* s) {
    asm volatile("cp.async.cg.shared.global [%0], [%1], 16;" :: "r"(d), "l"(s) : "memory");
}
__device__ __forceinline__ void ldm4(uint32_t* r, uint32_t addr) {
    asm volatile("ldmatrix.sync.aligned.m8n8.x4.shared.b16 {%0,%1,%2,%3}, [%4];"
                 : "=r"(r[0]), "=r"(r[1]), "=r"(r[2]), "=r"(r[3]) : "r"(addr));
}
__device__ __forceinline__ void mma16(float* c, const uint32_t* a, const uint32_t* b) {
    asm volatile(
        "mma.sync.aligned.m16n8k16.row.col.f32.f16.f16.f32 "
        "{%0,%1,%2,%3},{%4,%5,%6,%7},{%8,%9},{%0,%1,%2,%3};"
        : "+f"(c[0]), "+f"(c[1]), "+f"(c[2]), "+f"(c[3])
        : "r"(a[0]), "r"(a[1]), "r"(a[2]), "r"(a[3]), "r"(b[0]), "r"(b[1]));
}
__device__ __forceinline__ uint32_t hmul2u(uint32_t a, __half2 s) {
    __half2 r = __hmul2(*(__half2*)&a, s);
    return *(uint32_t*)&r;
}

// fp16 HMMA GEMM body, 512 threads = 16 warps (4M x 4N).
// FUSEA: A = eh2(M,2048); A[m,k] = atth[m,k>>10] * eh2[m, (k>=KBIG?1024:0)+(k&1023)]
template <int BM, int BN, int ACT, int OUTH, int FUSEA>
__device__ __forceinline__ void gemm_body(
    __half* sm, int bx, int by, int bz,
    const __half* __restrict__ A, const __half* __restrict__ W,
    const float* __restrict__ bias, void* __restrict__ Cv,
    int M, int N, int K, int kChunk, const __half* __restrict__ atth) {
    constexpr int S    = 4;
    constexpr int MT   = BM / 64;
    constexpr int NT   = BN / 32;
    constexpr int NP   = NT / 2;
    constexpr int STGH = (BM + BN) * 40;

    const uint32_t sb = smem_u32(sm);
    const int tid = threadIdx.x, lane = tid & 31, wid = tid >> 5;
    const int wm = wid & 3, wn = wid >> 2;
    const int grp = lane >> 2, qid = lane & 3;
    const int g = lane >> 3, lr = lane & 7;
    const int m0 = by * BM, n0 = bx * BN;
    const int kStart = bz * kChunk;
    const int T = kChunk / 32;

    const uint32_t aoff = (uint32_t)(wm * (BM / 4) + (g & 1) * 8 + lr) * 80u + (g >> 1) * 16u;
    const uint32_t boff = (uint32_t)(BM + wn * (BN / 4) + (g >> 1) * 8 + lr) * 80u + (g & 1) * 16u;

    float c[MT][NT][4];
#pragma unroll
    for (int i = 0; i < MT; i++)
#pragma unroll
        for (int j = 0; j < NT; j++)
#pragma unroll
            for (int q = 0; q < 4; q++) c[i][j][q] = 0.0f;

    auto stage = [&](int t, int s) {
        uint32_t base = sb + (uint32_t)(s * STGH) * 2u;
        const __half* Ap;
        size_t astr;
        if (FUSEA) {
            int k = kStart + t * 32;
            Ap = A + (size_t)m0 * 2048 + ((k >= KBIG) ? 1024 : 0) + (k & 1023);
            astr = 2048;
        } else {
            Ap = A + (size_t)m0 * K + kStart + t * 32;
            astr = K;
        }
        const __half* Wp = W + (size_t)n0 * K + kStart + t * 32;
#pragma unroll
        for (int c2 = tid; c2 < BM * 4; c2 += 512) {
            int row = c2 >> 2, q = c2 & 3;
            cp16(base + (uint32_t)(row * 80 + q * 16), Ap + (size_t)row * astr + q * 8);
        }
#pragma unroll
        for (int c2 = tid; c2 < BN * 4; c2 += 512) {
            int row = c2 >> 2, q = c2 & 3;
            cp16(base + (uint32_t)(BM * 80 + row * 80 + q * 16), Wp + (size_t)row * K + q * 8);
        }
        asm volatile("cp.async.commit_group;" ::: "memory");
    };

    for (int u = 0; u < S - 1 && u < T; u++) stage(u, u);

    int t = 0;
    while (t < T) {
        __half2 attv[MT][2];
        int tEnd;
        if (FUSEA) {
            int r = (kStart + (t << 5)) >> 10;
#pragma unroll
            for (int mt = 0; mt < MT; mt++) {
                int rowA = m0 + wm * (BM / 4) + mt * 16 + grp;
                attv[mt][0] = __half2half2(atth[rowA * 32 + r]);
                attv[mt][1] = __half2half2(atth[(rowA + 8) * 32 + r]);
            }
            int tNext = (((r + 1) << 10) - kStart) >> 5;
            tEnd = tNext < T ? tNext : T;
        } else {
            tEnd = T;
        }

        for (; t < tEnd; t++) {
            asm volatile("cp.async.wait_group %0;" :: "n"(S - 2));
            __syncthreads();
            if (t + S - 1 < T) stage(t + S - 1, (t + S - 1) % S);
            else asm volatile("cp.async.commit_group;" ::: "memory");

            const uint32_t stg = sb + (uint32_t)((t % S) * STGH) * 2u;
#pragma unroll
            for (int kk = 0; kk < 2; kk++) {
                uint32_t af[MT][4], bf[NP][4];
#pragma unroll
                for (int mt = 0; mt < MT; mt++) {
                    ldm4(af[mt], stg + aoff + (uint32_t)(mt * 16 * 80) + kk * 32u);
                    if (FUSEA) {
                        af[mt][0] = hmul2u(af[mt][0], attv[mt][0]);
                        af[mt][2] = hmul2u(af[mt][2], attv[mt][0]);
                        af[mt][1] = hmul2u(af[mt][1], attv[mt][1]);
                        af[mt][3] = hmul2u(af[mt][3], attv[mt][1]);
                    }
                }
#pragma unroll
                for (int p = 0; p < NP; p++)
                    ldm4(bf[p], stg + boff + (uint32_t)(p * 16 * 80) + kk * 32u);
#pragma unroll
                for (int mt = 0; mt < MT; mt++)
#pragma unroll
                    for (int nt = 0; nt < NT; nt++)
                        mma16(c[mt][nt], af[mt], &bf[nt >> 1][(nt & 1) * 2]);
            }
            __syncthreads();
        }
    }

#pragma unroll
    for (int mt = 0; mt < MT; mt++) {
#pragma unroll
        for (int nt = 0; nt < NT; nt++) {
            int row = m0 + wm * (BM / 4) + mt * 16 + grp;
            int col = n0 + wn * (BN / 4) + nt * 8 + qid * 2;
            float v0 = c[mt][nt][0], v1 = c[mt][nt][1];
            float v2 = c[mt][nt][2], v3 = c[mt][nt][3];
            if (bias) {
                float u0 = bias[col], u1 = bias[col + 1];
                v0 += u0; v1 += u1; v2 += u0; v3 += u1;
            }
            if (ACT == 1) {
                v0 = fmaxf(v0, 0.0f); v1 = fmaxf(v1, 0.0f);
                v2 = fmaxf(v2, 0.0f); v3 = fmaxf(v3, 0.0f);
            }
            if (OUTH) {
                __half* Ch = (__half*)Cv;
                *(__half2*)(&Ch[(size_t)row * N + col])       = __floats2half2_rn(v0, v1);
                *(__half2*)(&Ch[(size_t)(row + 8) * N + col]) = __floats2half2_rn(v2, v3);
            } else {
                float* Cf = (float*)Cv + (size_t)bz * M * N;
                *(float2*)(&Cf[(size_t)row * N + col])       = make_float2(v0, v1);
                *(float2*)(&Cf[(size_t)(row + 8) * N + col]) = make_float2(v2, v3);
            }
        }
    }
}

template <int BM, int BN, int ACT, int OUTH>
__global__ void __launch_bounds__(512, 1)
hgemm(const __half* __restrict__ A, const __half* __restrict__ W,
      const float* __restrict__ bias, void* __restrict__ Cv,
      int M, int N, int K, int kChunk) {
    extern __shared__ __align__(16) __half sm[];
    gemm_body<BM, BN, ACT, OUTH, 0>(sm, blockIdx.x, blockIdx.y, blockIdx.z,
                                    A, W, bias, Cv, M, N, K, kChunk, nullptr);
}

// blocks 0-255: G1 (128x128 tiles, split-K=4, 2 CTAs/SM); 256-383: G2;
// blocks 384+: w2/w0/wa1/wa2 fp16 copies (hidden in G1's shadow)
__global__ void __launch_bounds__(512, 2)
g1g2_kernel(const __half* __restrict__ eh2, const __half* __restrict__ WT,
            float* __restrict__ rt, const __half* __restrict__ atth,
            const __half* __restrict__ hin, const __half* __restrict__ w1,
            const float* __restrict__ b1, __half* __restrict__ h1,
            const float* s2, __half* d2, int n2,
            const float* s3, __half* d3, int n3,
            const float* s4, __half* d4, int n4,
            const float* s5, __half* d5, int n5) {
    extern __shared__ __align__(16) __half sm[];
    int bid = blockIdx.x;
    if (bid < 256) {
        gemm_body<128, 128, 0, 0, 1>(sm, bid & 7, (bid >> 3) & 7, bid >> 6,
                                     eh2, WT, nullptr, rt, BB, D2C, KBIG2, KBIG2 / G1Z, atth);
        return;
    }
    if (bid < 384) {
        int u = bid - 256;
        gemm_body<128, 128, 1, 1, 0>(sm, u & 15, u >> 4, 0,
                                     hin, w1, b1, h1, BB, HIDC, D2C, D2C, nullptr);
        return;
    }
    int base = (bid - 384) * 512 * 8 + threadIdx.x;
#pragma unroll
    for (int i = 0; i < 8; i++) {
        int off = base + i * 512;
        const float* s; __half* d;
        if (off < n2) { s = s2; d = d2; }
        else if ((off -= n2) < n3) { s = s3; d = d3; }
        else if ((off -= n3) < n4) { s = s4; d = d4; }
        else if ((off -= n4) < n5) { s = s5; d = d5; }
        else continue;
        float4 v = ((const float4*)s)[off];
        __half2* dd = (__half2*)d;
        dd[off * 2]     = __floats2half2_rn(v.x, v.y);
        dd[off * 2 + 1] = __floats2half2_rn(v.z, v.w);
    }
}

// blocks 0-127: G3 (h1@W2); 128-1151: ln_rtrans (one batch row each)
__global__ void __launch_bounds__(512, 1)
g3ln_kernel(const __half* __restrict__ h1, const __half* __restrict__ w2,
            const float* __restrict__ b2, __half* __restrict__ h2) {
    extern __shared__ __align__(16) __half sm[];
    int bid = blockIdx.x;
    if (bid < 128) {
        gemm_body<128, 128, 1, 1, 0>(sm, bid & 15, bid >> 4, 0,
                                     h1, w2, b2, h2, BB, HIDC, HIDC, HIDC, nullptr);
        return;
    }
    float* red = (float*)sm;
    int b = bid - 128, t = threadIdx.x;
    float v[2], s = 0.0f;
#pragma unroll
    for (int u = 0; u < 2; u++) {
        int i = t + u * 512;
        float x = 0.0f;
#pragma unroll
        for (int z = 0; z < G1Z; z++) x += g_rt[((size_t)z * BB + b) * D2C + i];
        v[u] = x; s += x;
    }
    red[t] = s; __syncthreads();
#pragma unroll
    for (int st = 256; st > 0; st >>= 1) { if (t < st) red[t] += red[t + st]; __syncthreads(); }
    float mean = red[0] * (1.0f / D2C); __syncthreads();
    float d = 0.0f;
#pragma unroll
    for (int u = 0; u < 2; u++) { float dv = v[u] - mean; d += dv * dv; }
    red[t] = d; __syncthreads();
#pragma unroll
    for (int st = 256; st > 0; st >>= 1) { if (t < st) red[t] += red[t + st]; __syncthreads(); }
    float inv = rsqrtf(red[0] * (1.0f / D2C) + LN_EPS_F);
#pragma unroll
    for (int u = 0; u < 2; u++)
        g_xstack[b * D2C + t + u * 512] = __float2half_rn((v[u] - mean) * inv);
}

// blocks 0-127: G4 (split-K=2); 128-191: G5a (rtrans rows of G5)
__global__ void __launch_bounds__(512, 1)
g4g5a_kernel(const __half* __restrict__ h2, const __half* __restrict__ w0,
             float* __restrict__ x0, const __half* __restrict__ xs,
             const __half* __restrict__ wa1, const float* __restrict__ ba1,
             __half* __restrict__ a) {
    extern __shared__ __align__(16) __half sm[];
    int bid = blockIdx.x;
    if (bid < 128) {
        gemm_body<128, 128, 0, 0, 0>(sm, bid & 7, (bid >> 3) & 7, bid >> 6,
                                     h2, w0, nullptr, x0, BB, D2C, HIDC, HIDC / 2, nullptr);
    } else {
        int u = bid - 128;
        gemm_body<64, 128, 1, 1, 0>(sm, u & 3, u >> 2, 0,
                                    xs, wa1, ba1, a, BB, DIMC, D2C, D2C, nullptr);
    }
}

// G6 + fuse: both branch score tiles (shared Wa2 B-tile) + softmax + output transforms
__global__ void __launch_bounds__(512, 1)
g6fuse_kernel(const __half* __restrict__ A, const __half* __restrict__ W,
              const float* __restrict__ ba2, float* __restrict__ out) {
    constexpr int S = 4;
    constexpr int STGH = 256 * 40;
    extern __shared__ __align__(16) __half sm[];
    const uint32_t sb = smem_u32(sm);
    const int tid = threadIdx.x, lane = tid & 31, wid = tid >> 5;
    const int wm = wid & 3, wn = wid >> 2;
    const int grp = lane >> 2, qid = lane & 3;
    const int g = lane >> 3, lr = lane & 7;
    const int m0 = blockIdx.y * 64, n0 = blockIdx.x * 128;
    const int T = DIMC / 32;

    const uint32_t a0off = (uint32_t)(wm * 16 + (g & 1) * 8 + lr) * 80u + (g >> 1) * 16u;
    const uint32_t a1off = a0off + 64u * 80u;
    const uint32_t boff  = (uint32_t)(128 + wn * 32 + (g >> 1) * 8 + lr) * 80u + (g & 1) * 16u;

    float c0[4][4], c1[4][4];
#pragma unroll
    for (int j = 0; j < 4; j++)
#pragma unroll
        for (int q = 0; q < 4; q++) { c0[j][q] = 0.0f; c1[j][q] = 0.0f; }

    auto stage = [&](int t, int s) {
        uint32_t base = sb + (uint32_t)(s * STGH) * 2u;
        const __half* A0 = A + (size_t)m0 * DIMC + t * 32;
        const __half* A1 = A + (size_t)(BB + m0) * DIMC + t * 32;
        const __half* Wp = W + (size_t)n0 * DIMC + t * 32;
#pragma unroll
        for (int c2 = tid; c2 < 64 * 4; c2 += 512) {
            int row = c2 >> 2, q = c2 & 3;
            cp16(base + (uint32_t)(row * 80 + q * 16), A0 + (size_t)row * DIMC + q * 8);
            cp16(base + (uint32_t)((row + 64) * 80 + q * 16), A1 + (size_t)row * DIMC + q * 8);
        }
#pragma unroll
        for (int c2 = tid; c2 < 128 * 4; c2 += 512) {
            int row = c2 >> 2, q = c2 & 3;
            cp16(base + (uint32_t)((row + 128) * 80 + q * 16), Wp + (size_t)row * DIMC + q * 8);
        }
        asm volatile("cp.async.commit_group;" ::: "memory");
    };

    for (int u = 0; u < S - 1 && u < T; u++) stage(u, u);

    for (int t = 0; t < T; t++) {
        asm volatile("cp.async.wait_group %0;" :: "n"(S - 2));
        __syncthreads();
        if (t + S - 1 < T) stage(t + S - 1, (t + S - 1) % S);
        else asm volatile("cp.async.commit_group;" ::: "memory");

        const uint32_t stg = sb + (uint32_t)((t % S) * STGH) * 2u;
#pragma unroll
        for (int kk = 0; kk < 2; kk++) {
            uint32_t a0f[4], a1f[4], bf[2][4];
            ldm4(a0f, stg + a0off + kk * 32u);
            ldm4(a1f, stg + a1off + kk * 32u);
#pragma unroll
            for (int p = 0; p < 2; p++)
                ldm4(bf[p], stg + boff + (uint32_t)(p * 16 * 80) + kk * 32u);
#pragma unroll
            for (int nt = 0; nt < 4; nt++) {
                mma16(c0[nt], a0f, &bf[nt >> 1][(nt & 1) * 2]);
                mma16(c1[nt], a1f, &bf[nt >> 1][(nt & 1) * 2]);
            }
        }
        __syncthreads();
    }

#pragma unroll
    for (int nt = 0; nt < 4; nt++) {
        int row = m0 + wm * 16 + grp;
        int col = n0 + wn * 32 + nt * 8 + qid * 2;
        float u0 = ba2[col], u1 = ba2[col + 1];
#pragma unroll
        for (int half = 0; half < 2; half++) {
            int r = row + half * 8;
            float s0a = c0[nt][half * 2] + u0, s0b = c0[nt][half * 2 + 1] + u1;
            float s1a = c1[nt][half * 2] + u0, s1b = c1[nt][half * 2 + 1] + u1;
            __half2 xr = *(const __half2*)&g_xstack[(size_t)r * D2C + col];
            __half2 xm = *(const __half2*)&g_xstack[(size_t)(BB + r) * D2C + col];
            float pa = 1.0f / (1.0f + expf(s1a - s0a));
            float pb = 1.0f / (1.0f + expf(s1b - s0b));
            float xa = pa * __low2float(xr) + (1.0f - pa) * __low2float(xm);
            float xb = pb * __high2float(xr) + (1.0f - pb) * __high2float(xm);
            float2 o;
            if (col < DIMC) {
                o.x = tanhf(xa) * PI_F;
                o.y = tanhf(xb) * PI_F;
                *(float2*)&out[(size_t)r * DIMC + col] = o;
            } else {
                o.x = tanhf(2.0f * xa) * (PI_F * 0.5f) + (PI_F * 0.5f);
                o.y = tanhf(2.0f * xb) * (PI_F * 0.5f) + (PI_F * 0.5f);
                *(float2*)&out[(size_t)BB * DIMC + (size_t)r * DIMC + (col - DIMC)] = o;
            }
        }
    }
}

// front kernel: transpose + rel_bias^T + prep + w1 copy (block ranges)
#define NTR ((KBIG / 32) * (D2C / 64))
#define NBI 120
#define NPR BB
__global__ void front_kernel(const float* __restrict__ rb, const float* __restrict__ rel_bias,
                             const float* __restrict__ ax, const float* __restrict__ ag,
                             const int* __restrict__ idx, const float* __restrict__ rel_att,
                             const float* __restrict__ rax, const float* __restrict__ rag,
                             const float* s1, __half* d1, int n1) {
    int bid = blockIdx.x, t = threadIdx.x;
    if (bid < NTR) {
        __shared__ float tile[32][67];
        int k0 = (bid % (KBIG / 32)) * 32, n0 = (bid / (KBIG / 32)) * 64;
#pragma unroll
        for (int i = 0; i < 2; i++) {
            int idx2 = t + i * 256;
            int row = idx2 >> 4, c4 = idx2 & 15;
            float4 v = *(const float4*)&rb[(size_t)(k0 + row) * D2C + n0 + c4 * 4];
            tile[row][c4 * 4 + 0] = v.x; tile[row][c4 * 4 + 1] = v.y;
            tile[row][c4 * 4 + 2] = v.z; tile[row][c4 * 4 + 3] = v.w;
        }
        __syncthreads();
        int n = t >> 2, kg = t & 3;
        __half hv[8];
#pragma unroll
        for (int j = 0; j < 8; j++) hv[j] = __float2half_rn(tile[kg * 8 + j][n]);
        *(uint4*)&g_WT[(size_t)(n0 + n) * KBIG2 + k0 + kg * 8] = *(uint4*)hv;
        return;
    }
    bid -= NTR;
    if (bid < NBI) {
        int idx2 = bid * 256 + t;
        if (idx2 < 30720) {
            int n = idx2 / 30, j = idx2 % 30;
            g_WT[(size_t)n * KBIG2 + KBIG + j] = __float2half_rn(rel_bias[j * D2C + n]);
        }
        return;
    }
    bid -= NBI;
    if (bid < NPR) {
        int b = bid;
        int rid = idx[b];
        if (t < 32) {
            float v = (t < NBASE) ? tanhf(rel_att[rid * NBASE + t] * INV_EMB) * PI_F : 0.0f;
            g_atth[b * 32 + t] = (t < NBASE) ? __float2half_rn(v) :
                                 (t == 30 ? __float2half_rn(1.0f) : __float2half_rn(0.0f));
            g_eh2[b * 2048 + 1024 + t] = __float2half_rn(v);
        }
        for (int j = t; j < DIMC; j += 256) {
            float a = ax[b * DIMC + j], g = ag[b * DIMC + j];
            g_eh2[b * 2048 + j]        = __float2half_rn(a);
            g_eh2[b * 2048 + DIMC + j] = __float2half_rn(g);
            float rx = tanhf(rax[rid * DIMC + j] * INV_EMB) * PI_F;
            float rg = tanhf(2.0f * (rag[rid * DIMC + j] * INV_EMB)) * (PI_F * 0.5f) + (PI_F * 0.5f);
            g_hin[b * D2C + j] = __float2half_rn(a + rx);
            g_hin[b * D2C + DIMC + j] = __float2half_rn(g + rg);
        }
        return;
    }
    bid -= NPR;
    int off = bid * 256 + t;
    if (off < n1) {
        float4 v = ((const float4*)s1)[off];
        __half2* dd = (__half2*)d1;
        dd[off * 2]     = __floats2half2_rn(v.x, v.y);
        dd[off * 2 + 1] = __floats2half2_rn(v.z, v.w);
    }
}

__device__ __forceinline__ float block_sum(float v, float* red) {
    int t = threadIdx.x;
    red[t] = v; __syncthreads();
#pragma unroll
    for (int s = 128; s > 0; s >>= 1) { if (t < s) red[t] += red[t + s]; __syncthreads(); }
    float r = red[0]; __syncthreads();
    return r;
}

__global__ void ln_mlp_kernel(const float* __restrict__ b0) {
    __shared__ float red[256];
    int b = blockIdx.x, t = threadIdx.x;
    float v[4], s = 0.0f;
#pragma unroll
    for (int u = 0; u < 4; u++) {
        int i = t + u * 256;
        v[u] = g_x0[b * D2C + i] + g_x0[(size_t)(BB + b) * D2C + i] + b0[i];
        s += v[u];
    }
    float mean = block_sum(s, red) * (1.0f / D2C);
    float d = 0.0f;
#pragma unroll
    for (int u = 0; u < 4; u++) { float dv = v[u] - mean; d += dv * dv; }
    float inv = rsqrtf(block_sum(d, red) * (1.0f / D2C) + LN_EPS_F);
#pragma unroll
    for (int u = 0; u < 4; u++)
        g_xstack[(size_t)(BB + b) * D2C + t + u * 256] = __float2half_rn((v[u] - mean) * inv);
}

extern "C" void kernel_launch(void* const* d_in, const int* in_sizes, int n_in,
                              void* d_out, int out_size) {
    const float* ax = (const float*)d_in[0];
    const float* ag = (const float*)d_in[1];
    const int* idx = (const int*)d_in[2];
    const float* rel_base = (const float*)d_in[3];
    const float* rel_att = (const float*)d_in[4];
    const float* rel_bias = (const float*)d_in[5];
    const float* rax = (const float*)d_in[6];
    const float* rag = (const float*)d_in[7];
    const float* W1 = (const float*)d_in[8];
    const float* b1 = (const float*)d_in[9];
    const float* W2 = (const float*)d_in[10];
    const float* b2 = (const float*)d_in[11];
    const float* W0 = (const float*)d_in[12];
    const float* b0 = (const float*)d_in[13];
    const float* Wa1 = (const float*)d_in[14];
    const float* ba1 = (const float*)d_in[15];
    const float* Wa2 = (const float*)d_in[16];
    const float* ba2 = (const float*)d_in[17];
    float* out = (float*)d_out;

    __half *pWT, *peh2, *path, *phin, *ph1, *ph2, *pxs, *pa;
    __half *pw1, *pw2, *pw0, *pwa1, *pwa2;
    float *prt, *px0;
    cudaGetSymbolAddress((void**)&pWT, g_WT);
    cudaGetSymbolAddress((void**)&peh2, g_eh2);
    cudaGetSymbolAddress((void**)&path, g_atth);
    cudaGetSymbolAddress((void**)&phin, g_hin);
    cudaGetSymbolAddress((void**)&ph1, g_h1);
    cudaGetSymbolAddress((void**)&ph2, g_h2);
    cudaGetSymbolAddress((void**)&pxs, g_xstack);
    cudaGetSymbolAddress((void**)&pa, g_a);
    cudaGetSymbolAddress((void**)&prt, g_rt);
    cudaGetSymbolAddress((void**)&px0, g_x0);
    cudaGetSymbolAddress((void**)&pw1, g_w1h);
    cudaGetSymbolAddress((void**)&pw2, g_w2h);
    cudaGetSymbolAddress((void**)&pw0, g_w0h);
    cudaGetSymbolAddress((void**)&pwa1, g_wa1h);
    cudaGetSymbolAddress((void**)&pwa2, g_wa2h);

    const int SMB128 = 4 * (128 + 128) * 40 * 2;  // 81920
    const int SMG6   = 4 * 256 * 40 * 2;          // 81920
    cudaFuncSetAttribute(g1g2_kernel,
                         cudaFuncAttributeMaxDynamicSharedMemorySize, SMB128);
    cudaFuncSetAttribute(g3ln_kernel,
                         cudaFuncAttributeMaxDynamicSharedMemorySize, SMB128);
    cudaFuncSetAttribute(g4g5a_kernel,
                         cudaFuncAttributeMaxDynamicSharedMemorySize, SMB128);
    cudaFuncSetAttribute(hgemm<64, 128, 1, 1>,
                         cudaFuncAttributeMaxDynamicSharedMemorySize, SMB128);
    cudaFuncSetAttribute(g6fuse_kernel,
                         cudaFuncAttributeMaxDynamicSharedMemorySize, SMG6);

    int n1 = HIDC * D2C / 4;
    int n2 = HIDC * HIDC / 4, n3 = D2C * HIDC / 4;
    int n4 = DIMC * D2C / 4, n5 = D2C * DIMC / 4;
    int ncopy1 = (n1 + 255) / 256;
    front_kernel<<<NTR + NBI + NPR + ncopy1, 256>>>(
        rel_base, rel_bias, ax, ag, idx, rel_att, rax, rag, W1, pw1, n1);

    // G1 (2 CTAs/SM experiment) + G2 + trailing weight copies
    int ncopy2 = (n2 + n3 + n4 + n5 + 512 * 8 - 1) / (512 * 8);
    g1g2_kernel<<<384 + ncopy2, 512, SMB128>>>(
        peh2, pWT, prt, path, phin, pw1, b1, ph1,
        W2, pw2, n2, W0, pw0, n3, Wa1, pwa1, n4, Wa2, pwa2, n5);

    // G3 + ln_rtrans (concurrent, disjoint data)
    g3ln_kernel<<<128 + BB, 512, SMB128>>>(ph1, pw2, b2, ph2);

    // G4 (split-K=2) + G5a (rtrans half of attention GEMM 1)
    g4g5a_kernel<<<128 + 64, 512, SMB128>>>(ph2, pw0, px0, pxs, pwa1, ba1, pa);
    ln_mlp_kernel<<<BB, 256>>>(b0);

    // G5b: mlp half
    hgemm<64, 128, 1, 1><<<dim3(DIMC / 128, BB / 64, 1), 512, SMB128>>>(
        pxs + (size_t)BB * D2C, pwa1, ba1, pa + (size_t)BB * DIMC,
        BB, DIMC, D2C, D2C);

    // G6 + softmax-fuse + output transforms
    g6fuse_kernel<<<dim3(D2C / 128, BB / 64), 512, SMG6>>>(pa, pwa2, ba2, out);
}

// round 14
// speedup vs baseline: 1.0503x; 1.0503x over previous
#include <cuda_runtime.h>
#include <cuda_fp16.h>
#include <math.h>
#include <stdint.h>

#define BB    1024
#define DIMC  512
#define D2C   1024
#define HIDC  2048
#define NBASE 30
#define KBIG  (NBASE * D2C)     // 30720
#define KBIG2 (KBIG + 1024)     // 31744 (incl. bias block r=30)
#define G1Z   4

#define PI_F      3.14159265358979323846f
#define INV_EMB   36.3636363636363636f
#define LN_EPS_F  1e-5f

__device__ __half g_atth[BB * 32];          // 0..29 att, 30 = 1.0, 31 = 0
__device__ __half g_eh2[BB * 2048];         // [0:1024) e, [1024:1056) att, rest 0
__device__ __half g_hin[BB * D2C];
__device__ __half g_WT[(size_t)D2C * KBIG2];
__device__ float  g_rt[(size_t)G1Z * BB * D2C];
__device__ __half g_h1[BB * HIDC];
__device__ __half g_h2[BB * HIDC];
__device__ float  g_x0[2 * BB * D2C];
__device__ __half g_xstack[2 * BB * D2C];
__device__ __half g_a[2 * BB * DIMC];
__device__ __half g_w1h[HIDC * D2C];
__device__ __half g_w2h[HIDC * HIDC];
__device__ __half g_w0h[D2C * HIDC];
__device__ __half g_wa1h[DIMC * D2C];
__device__ __half g_wa2h[D2C * DIMC];

__device__ __forceinline__ uint32_t smem_u32(const void* p) {
    uint32_t a;
    asm("{ .reg .u64 t; cvta.to.shared.u64 t, %1; cvt.u32.u64 %0, t; }" : "=r"(a) : "l"(p));
    return a;
}
__device__ __forceinline__ void cp16(uint32_t d, const void* s) {
    asm volatile("cp.async.cg.shared.global [%0], [%1], 16;" :: "r"(d), "l"(s) : "memory");
}
__device__ __forceinline__ void ldm4(uint32_t* r, uint32_t addr) {
    asm volatile("ldmatrix.sync.aligned.m8n8.x4.shared.b16 {%0,%1,%2,%3}, [%4];"
                 : "=r"(r[0]), "=r"(r[1]), "=r"(r[2]), "=r"(r[3]) : "r"(addr));
}
__device__ __forceinline__ void mma16(float* c, const uint32_t* a, const uint32_t* b) {
    asm volatile(
        "mma.sync.aligned.m16n8k16.row.col.f32.f16.f16.f32 "
        "{%0,%1,%2,%3},{%4,%5,%6,%7},{%8,%9},{%0,%1,%2,%3};"
        : "+f"(c[0]), "+f"(c[1]), "+f"(c[2]), "+f"(c[3])
        : "r"(a[0]), "r"(a[1]), "r"(a[2]), "r"(a[3]), "r"(b[0]), "r"(b[1]));
}
__device__ __forceinline__ uint32_t hmul2u(uint32_t a, __half2 s) {
    __half2 r = __hmul2(*(__half2*)&a, s);
    return *(uint32_t*)&r;
}

// fp16 HMMA GEMM body, 512 threads = 16 warps (4M x 4N).
// ONE __syncthreads per K-iteration: the top sync (post wait_group) also
// separates iter t-1's slot reads from iter t's stage() writes to that slot.
// FUSEA: A = eh2(M,2048); A[m,k] = atth[m,k>>10] * eh2[m, (k>=KBIG?1024:0)+(k&1023)]
template <int BM, int BN, int ACT, int OUTH, int FUSEA>
__device__ __forceinline__ void gemm_body(
    __half* sm, int bx, int by, int bz,
    const __half* __restrict__ A, const __half* __restrict__ W,
    const float* __restrict__ bias, void* __restrict__ Cv,
    int M, int N, int K, int kChunk, const __half* __restrict__ atth) {
    constexpr int S    = 4;
    constexpr int MT   = BM / 64;
    constexpr int NT   = BN / 32;
    constexpr int NP   = NT / 2;
    constexpr int STGH = (BM + BN) * 40;

    const uint32_t sb = smem_u32(sm);
    const int tid = threadIdx.x, lane = tid & 31, wid = tid >> 5;
    const int wm = wid & 3, wn = wid >> 2;
    const int grp = lane >> 2, qid = lane & 3;
    const int g = lane >> 3, lr = lane & 7;
    const int m0 = by * BM, n0 = bx * BN;
    const int kStart = bz * kChunk;
    const int T = kChunk / 32;

    const uint32_t aoff = (uint32_t)(wm * (BM / 4) + (g & 1) * 8 + lr) * 80u + (g >> 1) * 16u;
    const uint32_t boff = (uint32_t)(BM + wn * (BN / 4) + (g >> 1) * 8 + lr) * 80u + (g & 1) * 16u;

    float c[MT][NT][4];
#pragma unroll
    for (int i = 0; i < MT; i++)
#pragma unroll
        for (int j = 0; j < NT; j++)
#pragma unroll
            for (int q = 0; q < 4; q++) c[i][j][q] = 0.0f;

    auto stage = [&](int t, int s) {
        uint32_t base = sb + (uint32_t)(s * STGH) * 2u;
        const __half* Ap;
        size_t astr;
        if (FUSEA) {
            int k = kStart + t * 32;
            Ap = A + (size_t)m0 * 2048 + ((k >= KBIG) ? 1024 : 0) + (k & 1023);
            astr = 2048;
        } else {
            Ap = A + (size_t)m0 * K + kStart + t * 32;
            astr = K;
        }
        const __half* Wp = W + (size_t)n0 * K + kStart + t * 32;
#pragma unroll
        for (int c2 = tid; c2 < BM * 4; c2 += 512) {
            int row = c2 >> 2, q = c2 & 3;
            cp16(base + (uint32_t)(row * 80 + q * 16), Ap + (size_t)row * astr + q * 8);
        }
#pragma unroll
        for (int c2 = tid; c2 < BN * 4; c2 += 512) {
            int row = c2 >> 2, q = c2 & 3;
            cp16(base + (uint32_t)(BM * 80 + row * 80 + q * 16), Wp + (size_t)row * K + q * 8);
        }
        asm volatile("cp.async.commit_group;" ::: "memory");
    };

    for (int u = 0; u < S - 1 && u < T; u++) stage(u, u);

    int t = 0;
    while (t < T) {
        __half2 attv[MT][2];
        int tEnd;
        if (FUSEA) {
            int r = (kStart + (t << 5)) >> 10;
#pragma unroll
            for (int mt = 0; mt < MT; mt++) {
                int rowA = m0 + wm * (BM / 4) + mt * 16 + grp;
                attv[mt][0] = __half2half2(atth[rowA * 32 + r]);
                attv[mt][1] = __half2half2(atth[(rowA + 8) * 32 + r]);
            }
            int tNext = (((r + 1) << 10) - kStart) >> 5;
            tEnd = tNext < T ? tNext : T;
        } else {
            tEnd = T;
        }

        for (; t < tEnd; t++) {
            asm volatile("cp.async.wait_group %0;" :: "n"(S - 2));
            __syncthreads();   // publishes slot t%S AND guards slot (t-1)%S rewrite
            if (t + S - 1 < T) stage(t + S - 1, (t + S - 1) % S);
            else asm volatile("cp.async.commit_group;" ::: "memory");

            const uint32_t stg = sb + (uint32_t)((t % S) * STGH) * 2u;
#pragma unroll
            for (int kk = 0; kk < 2; kk++) {
                uint32_t af[MT][4], bf[NP][4];
#pragma unroll
                for (int mt = 0; mt < MT; mt++) {
                    ldm4(af[mt], stg + aoff + (uint32_t)(mt * 16 * 80) + kk * 32u);
                    if (FUSEA) {
                        af[mt][0] = hmul2u(af[mt][0], attv[mt][0]);
                        af[mt][2] = hmul2u(af[mt][2], attv[mt][0]);
                        af[mt][1] = hmul2u(af[mt][1], attv[mt][1]);
                        af[mt][3] = hmul2u(af[mt][3], attv[mt][1]);
                    }
                }
#pragma unroll
                for (int p = 0; p < NP; p++)
                    ldm4(bf[p], stg + boff + (uint32_t)(p * 16 * 80) + kk * 32u);
#pragma unroll
                for (int mt = 0; mt < MT; mt++)
#pragma unroll
                    for (int nt = 0; nt < NT; nt++)
                        mma16(c[mt][nt], af[mt], &bf[nt >> 1][(nt & 1) * 2]);
            }
            // no bottom sync: next iteration's top sync covers slot reuse
        }
    }

#pragma unroll
    for (int mt = 0; mt < MT; mt++) {
#pragma unroll
        for (int nt = 0; nt < NT; nt++) {
            int row = m0 + wm * (BM / 4) + mt * 16 + grp;
            int col = n0 + wn * (BN / 4) + nt * 8 + qid * 2;
            float v0 = c[mt][nt][0], v1 = c[mt][nt][1];
            float v2 = c[mt][nt][2], v3 = c[mt][nt][3];
            if (bias) {
                float u0 = bias[col], u1 = bias[col + 1];
                v0 += u0; v1 += u1; v2 += u0; v3 += u1;
            }
            if (ACT == 1) {
                v0 = fmaxf(v0, 0.0f); v1 = fmaxf(v1, 0.0f);
                v2 = fmaxf(v2, 0.0f); v3 = fmaxf(v3, 0.0f);
            }
            if (OUTH) {
                __half* Ch = (__half*)Cv;
                *(__half2*)(&Ch[(size_t)row * N + col])       = __floats2half2_rn(v0, v1);
                *(__half2*)(&Ch[(size_t)(row + 8) * N + col]) = __floats2half2_rn(v2, v3);
            } else {
                float* Cf = (float*)Cv + (size_t)bz * M * N;
                *(float2*)(&Cf[(size_t)row * N + col])       = make_float2(v0, v1);
                *(float2*)(&Cf[(size_t)(row + 8) * N + col]) = make_float2(v2, v3);
            }
        }
    }
}

template <int BM, int BN, int ACT, int OUTH>
__global__ void __launch_bounds__(512, 1)
hgemm(const __half* __restrict__ A, const __half* __restrict__ W,
      const float* __restrict__ bias, void* __restrict__ Cv,
      int M, int N, int K, int kChunk) {
    extern __shared__ __align__(16) __half sm[];
    gemm_body<BM, BN, ACT, OUTH, 0>(sm, blockIdx.x, blockIdx.y, blockIdx.z,
                                    A, W, bias, Cv, M, N, K, kChunk, nullptr);
}

// blocks 0-127: G1 (fused rtrans + bias, split-K=4); 128-255: G2 (MLP layer 1)
__global__ void __launch_bounds__(512, 1)
g1g2_kernel(const __half* __restrict__ eh2, const __half* __restrict__ WT,
            float* __restrict__ rt, const __half* __restrict__ atth,
            const __half* __restrict__ hin, const __half* __restrict__ w1,
            const float* __restrict__ b1, __half* __restrict__ h1) {
    extern __shared__ __align__(16) __half sm[];
    int bid = blockIdx.x;
    if (bid < 128) {
        gemm_body<128, 256, 0, 0, 1>(sm, bid & 3, (bid >> 2) & 7, bid >> 5,
                                     eh2, WT, nullptr, rt, BB, D2C, KBIG2, KBIG2 / G1Z, atth);
    } else {
        int u = bid - 128;
        gemm_body<128, 128, 1, 1, 0>(sm, u & 15, u >> 4, 0,
                                     hin, w1, b1, h1, BB, HIDC, D2C, D2C, nullptr);
    }
}

// blocks 0-127: G3 (h1@W2); 128-1151: ln_rtrans (one batch row each)
__global__ void __launch_bounds__(512, 1)
g3ln_kernel(const __half* __restrict__ h1, const __half* __restrict__ w2,
            const float* __restrict__ b2, __half* __restrict__ h2) {
    extern __shared__ __align__(16) __half sm[];
    int bid = blockIdx.x;
    if (bid < 128) {
        gemm_body<128, 128, 1, 1, 0>(sm, bid & 15, bid >> 4, 0,
                                     h1, w2, b2, h2, BB, HIDC, HIDC, HIDC, nullptr);
        return;
    }
    float* red = (float*)sm;
    int b = bid - 128, t = threadIdx.x;
    float v[2], s = 0.0f;
#pragma unroll
    for (int u = 0; u < 2; u++) {
        int i = t + u * 512;
        float x = 0.0f;
#pragma unroll
        for (int z = 0; z < G1Z; z++) x += g_rt[((size_t)z * BB + b) * D2C + i];
        v[u] = x; s += x;
    }
    red[t] = s; __syncthreads();
#pragma unroll
    for (int st = 256; st > 0; st >>= 1) { if (t < st) red[t] += red[t + st]; __syncthreads(); }
    float mean = red[0] * (1.0f / D2C); __syncthreads();
    float d = 0.0f;
#pragma unroll
    for (int u = 0; u < 2; u++) { float dv = v[u] - mean; d += dv * dv; }
    red[t] = d; __syncthreads();
#pragma unroll
    for (int st = 256; st > 0; st >>= 1) { if (t < st) red[t] += red[t + st]; __syncthreads(); }
    float inv = rsqrtf(red[0] * (1.0f / D2C) + LN_EPS_F);
#pragma unroll
    for (int u = 0; u < 2; u++)
        g_xstack[b * D2C + t + u * 512] = __float2half_rn((v[u] - mean) * inv);
}

// G6 + fuse: both branch score tiles (shared Wa2 B-tile) + softmax + output transforms
__global__ void __launch_bounds__(512, 1)
g6fuse_kernel(const __half* __restrict__ A, const __half* __restrict__ W,
              const float* __restrict__ ba2, float* __restrict__ out) {
    constexpr int S = 4;
    constexpr int STGH = 256 * 40;
    extern __shared__ __align__(16) __half sm[];
    const uint32_t sb = smem_u32(sm);
    const int tid = threadIdx.x, lane = tid & 31, wid = tid >> 5;
    const int wm = wid & 3, wn = wid >> 2;
    const int grp = lane >> 2, qid = lane & 3;
    const int g = lane >> 3, lr = lane & 7;
    const int m0 = blockIdx.y * 64, n0 = blockIdx.x * 128;
    const int T = DIMC / 32;

    const uint32_t a0off = (uint32_t)(wm * 16 + (g & 1) * 8 + lr) * 80u + (g >> 1) * 16u;
    const uint32_t a1off = a0off + 64u * 80u;
    const uint32_t boff  = (uint32_t)(128 + wn * 32 + (g >> 1) * 8 + lr) * 80u + (g & 1) * 16u;

    float c0[4][4], c1[4][4];
#pragma unroll
    for (int j = 0; j < 4; j++)
#pragma unroll
        for (int q = 0; q < 4; q++) { c0[j][q] = 0.0f; c1[j][q] = 0.0f; }

    auto stage = [&](int t, int s) {
        uint32_t base = sb + (uint32_t)(s * STGH) * 2u;
        const __half* A0 = A + (size_t)m0 * DIMC + t * 32;
        const __half* A1 = A + (size_t)(BB + m0) * DIMC + t * 32;
        const __half* Wp = W + (size_t)n0 * DIMC + t * 32;
#pragma unroll
        for (int c2 = tid; c2 < 64 * 4; c2 += 512) {
            int row = c2 >> 2, q = c2 & 3;
            cp16(base + (uint32_t)(row * 80 + q * 16), A0 + (size_t)row * DIMC + q * 8);
            cp16(base + (uint32_t)((row + 64) * 80 + q * 16), A1 + (size_t)row * DIMC + q * 8);
        }
#pragma unroll
        for (int c2 = tid; c2 < 128 * 4; c2 += 512) {
            int row = c2 >> 2, q = c2 & 3;
            cp16(base + (uint32_t)((row + 128) * 80 + q * 16), Wp + (size_t)row * DIMC + q * 8);
        }
        asm volatile("cp.async.commit_group;" ::: "memory");
    };

    for (int u = 0; u < S - 1 && u < T; u++) stage(u, u);

    for (int t = 0; t < T; t++) {
        asm volatile("cp.async.wait_group %0;" :: "n"(S - 2));
        __syncthreads();
        if (t + S - 1 < T) stage(t + S - 1, (t + S - 1) % S);
        else asm volatile("cp.async.commit_group;" ::: "memory");

        const uint32_t stg = sb + (uint32_t)((t % S) * STGH) * 2u;
#pragma unroll
        for (int kk = 0; kk < 2; kk++) {
            uint32_t a0f[4], a1f[4], bf[2][4];
            ldm4(a0f, stg + a0off + kk * 32u);
            ldm4(a1f, stg + a1off + kk * 32u);
#pragma unroll
            for (int p = 0; p < 2; p++)
                ldm4(bf[p], stg + boff + (uint32_t)(p * 16 * 80) + kk * 32u);
#pragma unroll
            for (int nt = 0; nt < 4; nt++) {
                mma16(c0[nt], a0f, &bf[nt >> 1][(nt & 1) * 2]);
                mma16(c1[nt], a1f, &bf[nt >> 1][(nt & 1) * 2]);
            }
        }
        // no bottom sync (see gemm_body)
    }

#pragma unroll
    for (int nt = 0; nt < 4; nt++) {
        int row = m0 + wm * 16 + grp;
        int col = n0 + wn * 32 + nt * 8 + qid * 2;
        float u0 = ba2[col], u1 = ba2[col + 1];
#pragma unroll
        for (int half = 0; half < 2; half++) {
            int r = row + half * 8;
            float s0a = c0[nt][half * 2] + u0, s0b = c0[nt][half * 2 + 1] + u1;
            float s1a = c1[nt][half * 2] + u0, s1b = c1[nt][half * 2 + 1] + u1;
            __half2 xr = *(const __half2*)&g_xstack[(size_t)r * D2C + col];
            __half2 xm = *(const __half2*)&g_xstack[(size_t)(BB + r) * D2C + col];
            float pa = 1.0f / (1.0f + expf(s1a - s0a));
            float pb = 1.0f / (1.0f + expf(s1b - s0b));
            float xa = pa * __low2float(xr) + (1.0f - pa) * __low2float(xm);
            float xb = pb * __high2float(xr) + (1.0f - pb) * __high2float(xm);
            float2 o;
            if (col < DIMC) {
                o.x = tanhf(xa) * PI_F;
                o.y = tanhf(xb) * PI_F;
                *(float2*)&out[(size_t)r * DIMC + col] = o;
            } else {
                o.x = tanhf(2.0f * xa) * (PI_F * 0.5f) + (PI_F * 0.5f);
                o.y = tanhf(2.0f * xb) * (PI_F * 0.5f) + (PI_F * 0.5f);
                *(float2*)&out[(size_t)BB * DIMC + (size_t)r * DIMC + (col - DIMC)] = o;
            }
        }
    }
}

// front kernel: transpose + rel_bias^T + prep + weight copies (block ranges)
#define NTR ((KBIG / 32) * (D2C / 64))
#define NBI 120
#define NPR BB
__global__ void front_kernel(const float* __restrict__ rb, const float* __restrict__ rel_bias,
                             const float* __restrict__ ax, const float* __restrict__ ag,
                             const int* __restrict__ idx, const float* __restrict__ rel_att,
                             const float* __restrict__ rax, const float* __restrict__ rag,
                             const float* s1, __half* d1, int n1,
                             const float* s2, __half* d2, int n2,
                             const float* s3, __half* d3, int n3,
                             const float* s4, __half* d4, int n4,
                             const float* s5, __half* d5, int n5) {
    int bid = blockIdx.x, t = threadIdx.x;
    if (bid < NTR) {
        __shared__ float tile[32][67];
        int k0 = (bid % (KBIG / 32)) * 32, n0 = (bid / (KBIG / 32)) * 64;
#pragma unroll
        for (int i = 0; i < 2; i++) {
            int idx2 = t + i * 256;
            int row = idx2 >> 4, c4 = idx2 & 15;
            float4 v = *(const float4*)&rb[(size_t)(k0 + row) * D2C + n0 + c4 * 4];
            tile[row][c4 * 4 + 0] = v.x; tile[row][c4 * 4 + 1] = v.y;
            tile[row][c4 * 4 + 2] = v.z; tile[row][c4 * 4 + 3] = v.w;
        }
        __syncthreads();
        int n = t >> 2, kg = t & 3;
        __half hv[8];
#pragma unroll
        for (int j = 0; j < 8; j++) hv[j] = __float2half_rn(tile[kg * 8 + j][n]);
        *(uint4*)&g_WT[(size_t)(n0 + n) * KBIG2 + k0 + kg * 8] = *(uint4*)hv;
        return;
    }
    bid -= NTR;
    if (bid < NBI) {
        int idx2 = bid * 256 + t;
        if (idx2 < 30720) {
            int n = idx2 / 30, j = idx2 % 30;
            g_WT[(size_t)n * KBIG2 + KBIG + j] = __float2half_rn(rel_bias[j * D2C + n]);
        }
        return;
    }
    bid -= NBI;
    if (bid < NPR) {
        int b = bid;
        int rid = idx[b];
        if (t < 32) {
            float v = (t < NBASE) ? tanhf(rel_att[rid * NBASE + t] * INV_EMB) * PI_F : 0.0f;
            g_atth[b * 32 + t] = (t < NBASE) ? __float2half_rn(v) :
                                 (t == 30 ? __float2half_rn(1.0f) : __float2half_rn(0.0f));
            g_eh2[b * 2048 + 1024 + t] = __float2half_rn(v);
        }
        for (int j = t; j < DIMC; j += 256) {
            float a = ax[b * DIMC + j], g = ag[b * DIMC + j];
            g_eh2[b * 2048 + j]        = __float2half_rn(a);
            g_eh2[b * 2048 + DIMC + j] = __float2half_rn(g);
            float rx = tanhf(rax[rid * DIMC + j] * INV_EMB) * PI_F;
            float rg = tanhf(2.0f * (rag[rid * DIMC + j] * INV_EMB)) * (PI_F * 0.5f) + (PI_F * 0.5f);
            g_hin[b * D2C + j] = __float2half_rn(a + rx);
            g_hin[b * D2C + DIMC + j] = __float2half_rn(g + rg);
        }
        return;
    }
    bid -= NPR;
    int i = bid * 256 + t;
    const float* s; __half* d; int off = i;
    if (off < n1) { s = s1; d = d1; }
    else if ((off -= n1) < n2) { s = s2; d = d2; }
    else if ((off -= n2) < n3) { s = s3; d = d3; }
    else if ((off -= n3) < n4) { s = s4; d = d4; }
    else if ((off -= n4) < n5) { s = s5; d = d5; }
    else return;
    float4 v = ((const float4*)s)[off];
    __half2* dd = (__half2*)d;
    dd[off * 2]     = __floats2half2_rn(v.x, v.y);
    dd[off * 2 + 1] = __floats2half2_rn(v.z, v.w);
}

__device__ __forceinline__ float block_sum(float v, float* red) {
    int t = threadIdx.x;
    red[t] = v; __syncthreads();
#pragma unroll
    for (int s = 128; s > 0; s >>= 1) { if (t < s) red[t] += red[t + s]; __syncthreads(); }
    float r = red[0]; __syncthreads();
    return r;
}

__global__ void ln_mlp_kernel(const float* __restrict__ b0) {
    __shared__ float red[256];
    int b = blockIdx.x, t = threadIdx.x;
    float v[4], s = 0.0f;
#pragma unroll
    for (int u = 0; u < 4; u++) {
        int i = t + u * 256;
        v[u] = g_x0[b * D2C + i] + g_x0[(size_t)(BB + b) * D2C + i] + b0[i];
        s += v[u];
    }
    float mean = block_sum(s, red) * (1.0f / D2C);
    float d = 0.0f;
#pragma unroll
    for (int u = 0; u < 4; u++) { float dv = v[u] - mean; d += dv * dv; }
    float inv = rsqrtf(block_sum(d, red) * (1.0f / D2C) + LN_EPS_F);
#pragma unroll
    for (int u = 0; u < 4; u++)
        g_xstack[(size_t)(BB + b) * D2C + t + u * 256] = __float2half_rn((v[u] - mean) * inv);
}

extern "C" void kernel_launch(void* const* d_in, const int* in_sizes, int n_in,
                              void* d_out, int out_size) {
    const float* ax = (const float*)d_in[0];
    const float* ag = (const float*)d_in[1];
    const int* idx = (const int*)d_in[2];
    const float* rel_base = (const float*)d_in[3];
    const float* rel_att = (const float*)d_in[4];
    const float* rel_bias = (const float*)d_in[5];
    const float* rax = (const float*)d_in[6];
    const float* rag = (const float*)d_in[7];
    const float* W1 = (const float*)d_in[8];
    const float* b1 = (const float*)d_in[9];
    const float* W2 = (const float*)d_in[10];
    const float* b2 = (const float*)d_in[11];
    const float* W0 = (const float*)d_in[12];
    const float* b0 = (const float*)d_in[13];
    const float* Wa1 = (const float*)d_in[14];
    const float* ba1 = (const float*)d_in[15];
    const float* Wa2 = (const float*)d_in[16];
    const float* ba2 = (const float*)d_in[17];
    float* out = (float*)d_out;

    __half *pWT, *peh2, *path, *phin, *ph1, *ph2, *pxs, *pa;
    __half *pw1, *pw2, *pw0, *pwa1, *pwa2;
    float *prt, *px0;
    cudaGetSymbolAddress((void**)&pWT, g_WT);
    cudaGetSymbolAddress((void**)&peh2, g_eh2);
    cudaGetSymbolAddress((void**)&path, g_atth);
    cudaGetSymbolAddress((void**)&phin, g_hin);
    cudaGetSymbolAddress((void**)&ph1, g_h1);
    cudaGetSymbolAddress((void**)&ph2, g_h2);
    cudaGetSymbolAddress((void**)&pxs, g_xstack);
    cudaGetSymbolAddress((void**)&pa, g_a);
    cudaGetSymbolAddress((void**)&prt, g_rt);
    cudaGetSymbolAddress((void**)&px0, g_x0);
    cudaGetSymbolAddress((void**)&pw1, g_w1h);
    cudaGetSymbolAddress((void**)&pw2, g_w2h);
    cudaGetSymbolAddress((void**)&pw0, g_w0h);
    cudaGetSymbolAddress((void**)&pwa1, g_wa1h);
    cudaGetSymbolAddress((void**)&pwa2, g_wa2h);

    const int SMB256 = 4 * (128 + 256) * 40 * 2;  // 122880
    const int SMB128 = 4 * (128 + 128) * 40 * 2;  // 81920
    const int SMB64  = 4 * (64 + 128) * 40 * 2;   // 61440
    const int SMG6   = 4 * 256 * 40 * 2;          // 81920
    cudaFuncSetAttribute(g1g2_kernel,
                         cudaFuncAttributeMaxDynamicSharedMemorySize, SMB256);
    cudaFuncSetAttribute(g3ln_kernel,
                         cudaFuncAttributeMaxDynamicSharedMemorySize, SMB128);
    cudaFuncSetAttribute(hgemm<128, 128, 0, 0>,
                         cudaFuncAttributeMaxDynamicSharedMemorySize, SMB128);
    cudaFuncSetAttribute(hgemm<64, 128, 1, 1>,
                         cudaFuncAttributeMaxDynamicSharedMemorySize, SMB64);
    cudaFuncSetAttribute(g6fuse_kernel,
                         cudaFuncAttributeMaxDynamicSharedMemorySize, SMG6);

    int n1 = HIDC * D2C / 4, n2 = HIDC * HIDC / 4, n3 = D2C * HIDC / 4;
    int n4 = DIMC * D2C / 4, n5 = D2C * DIMC / 4;
    int ncopy = (n1 + n2 + n3 + n4 + n5 + 255) / 256;
    front_kernel<<<NTR + NBI + NPR + ncopy, 256>>>(
        rel_base, rel_bias, ax, ag, idx, rel_att, rax, rag,
        W1, pw1, n1, W2, pw2, n2, W0, pw0, n3, Wa1, pwa1, n4, Wa2, pwa2, n5);

    // G1 (fused rtrans + bias, split-K=4) + G2
    g1g2_kernel<<<256, 512, SMB256>>>(peh2, pWT, prt, path, phin, pw1, b1, ph1);

    // G3 + ln_rtrans (concurrent, disjoint data)
    g3ln_kernel<<<128 + BB, 512, SMB128>>>(ph1, pw2, b2, ph2);

    // G4: h2 @ W0 -> x0 partials (split-K=2); b0 + sum folded in ln_mlp
    hgemm<128, 128, 0, 0><<<dim3(D2C / 128, BB / 128, 2), 512, SMB128>>>(
        ph2, pw0, nullptr, px0, BB, D2C, HIDC, HIDC / 2);
    ln_mlp_kernel<<<BB, 256>>>(b0);

    // G5: xstack(2048,1024) @ Wa1 -> a (fp16, relu)
    hgemm<64, 128, 1, 1><<<dim3(DIMC / 128, 2 * BB / 64, 1), 512, SMB64>>>(
        pxs, pwa1, ba1, pa, 2 * BB, DIMC, D2C, D2C);

    // G6 + softmax-fuse + output transforms
    g6fuse_kernel<<<dim3(D2C / 128, BB / 64), 512, SMG6>>>(pa, pwa2, ba2, out);
}

// round 15
// speedup vs baseline: 1.1164x; 1.0629x over previous
#include <cuda_runtime.h>
#include <cuda_fp16.h>
#include <math.h>
#include <stdint.h>

#define BB    1024
#define DIMC  512
#define D2C   1024
#define HIDC  2048
#define NBASE 30
#define KBIG  (NBASE * D2C)     // 30720
#define KBIG2 (KBIG + 1024)     // 31744 (incl. bias block r=30)
#define G1Z   4

#define PI_F      3.14159265358979323846f
#define INV_EMB   36.3636363636363636f
#define LN_EPS_F  1e-5f

__device__ __half g_atth[BB * 32];
__device__ __half g_eh2[BB * 2048];
__device__ __half g_hin[BB * D2C];
__device__ __half g_WT[(size_t)D2C * KBIG2];
__device__ float  g_rt[(size_t)G1Z * BB * D2C];
__device__ __half g_h1[BB * HIDC];
__device__ __half g_h2[BB * HIDC];
__device__ float  g_x0[2 * BB * D2C];
__device__ __half g_xstack[2 * BB * D2C];
__device__ __half g_a[2 * BB * DIMC];
__device__ __half g_w1h[HIDC * D2C];
__device__ __half g_w2h[HIDC * HIDC];
__device__ __half g_w0h[D2C * HIDC];
__device__ __half g_wa1h[DIMC * D2C];
__device__ __half g_wa2h[D2C * DIMC];

__device__ __forceinline__ uint32_t smem_u32(const void* p) {
    uint32_t a;
    asm("{ .reg .u64 t; cvta.to.shared.u64 t, %1; cvt.u32.u64 %0, t; }" : "=r"(a) : "l"(p));
    return a;
}
__device__ __forceinline__ void cp16(uint32_t d, const void* s) {
    asm volatile("cp.async.cg.shared.global [%0], [%1], 16;" :: "r"(d), "l"(s) : "memory");
}
__device__ __forceinline__ void ldm4(uint32_t* r, uint32_t addr) {
    asm volatile("ldmatrix.sync.aligned.m8n8.x4.shared.b16 {%0,%1,%2,%3}, [%4];"
                 : "=r"(r[0]), "=r"(r[1]), "=r"(r[2]), "=r"(r[3]) : "r"(addr));
}
__device__ __forceinline__ void mma16(float* c, const uint32_t* a, const uint32_t* b) {
    asm volatile(
        "mma.sync.aligned.m16n8k16.row.col.f32.f16.f16.f32 "
        "{%0,%1,%2,%3},{%4,%5,%6,%7},{%8,%9},{%0,%1,%2,%3};"
        : "+f"(c[0]), "+f"(c[1]), "+f"(c[2]), "+f"(c[3])
        : "r"(a[0]), "r"(a[1]), "r"(a[2]), "r"(a[3]), "r"(b[0]), "r"(b[1]));
}
__device__ __forceinline__ uint32_t hmul2u(uint32_t a, __half2 s) {
    __half2 r = __hmul2(*(__half2*)&a, s);
    return *(uint32_t*)&r;
}

// fp16 HMMA GEMM body, 512 threads = 16 warps (4M x 4N), one sync/iter.
template <int BM, int BN, int ACT, int OUTH, int FUSEA>
__device__ __forceinline__ void gemm_body(
    __half* sm, int bx, int by, int bz,
    const __half* __restrict__ A, const __half* __restrict__ W,
    const float* __restrict__ bias, void* __restrict__ Cv,
    int M, int N, int K, int kChunk, const __half* __restrict__ atth) {
    constexpr int S    = 4;
    constexpr int MT   = BM / 64;
    constexpr int NT   = BN / 32;
    constexpr int NP   = NT / 2;
    constexpr int STGH = (BM + BN) * 40;

    const uint32_t sb = smem_u32(sm);
    const int tid = threadIdx.x, lane = tid & 31, wid = tid >> 5;
    const int wm = wid & 3, wn = wid >> 2;
    const int grp = lane >> 2, qid = lane & 3;
    const int g = lane >> 3, lr = lane & 7;
    const int m0 = by * BM, n0 = bx * BN;
    const int kStart = bz * kChunk;
    const int T = kChunk / 32;

    const uint32_t aoff = (uint32_t)(wm * (BM / 4) + (g & 1) * 8 + lr) * 80u + (g >> 1) * 16u;
    const uint32_t boff = (uint32_t)(BM + wn * (BN / 4) + (g >> 1) * 8 + lr) * 80u + (g & 1) * 16u;

    float c[MT][NT][4];
#pragma unroll
    for (int i = 0; i < MT; i++)
#pragma unroll
        for (int j = 0; j < NT; j++)
#pragma unroll
            for (int q = 0; q < 4; q++) c[i][j][q] = 0.0f;

    auto stage = [&](int t, int s) {
        uint32_t base = sb + (uint32_t)(s * STGH) * 2u;
        const __half* Ap;
        size_t astr;
        if (FUSEA) {
            int k = kStart + t * 32;
            Ap = A + (size_t)m0 * 2048 + ((k >= KBIG) ? 1024 : 0) + (k & 1023);
            astr = 2048;
        } else {
            Ap = A + (size_t)m0 * K + kStart + t * 32;
            astr = K;
        }
        const __half* Wp = W + (size_t)n0 * K + kStart + t * 32;
#pragma unroll
        for (int c2 = tid; c2 < BM * 4; c2 += 512) {
            int row = c2 >> 2, q = c2 & 3;
            cp16(base + (uint32_t)(row * 80 + q * 16), Ap + (size_t)row * astr + q * 8);
        }
#pragma unroll
        for (int c2 = tid; c2 < BN * 4; c2 += 512) {
            int row = c2 >> 2, q = c2 & 3;
            cp16(base + (uint32_t)(BM * 80 + row * 80 + q * 16), Wp + (size_t)row * K + q * 8);
        }
        asm volatile("cp.async.commit_group;" ::: "memory");
    };

    for (int u = 0; u < S - 1 && u < T; u++) stage(u, u);

    int t = 0;
    while (t < T) {
        __half2 attv[MT][2];
        int tEnd;
        if (FUSEA) {
            int r = (kStart + (t << 5)) >> 10;
#pragma unroll
            for (int mt = 0; mt < MT; mt++) {
                int rowA = m0 + wm * (BM / 4) + mt * 16 + grp;
                attv[mt][0] = __half2half2(atth[rowA * 32 + r]);
                attv[mt][1] = __half2half2(atth[(rowA + 8) * 32 + r]);
            }
            int tNext = (((r + 1) << 10) - kStart) >> 5;
            tEnd = tNext < T ? tNext : T;
        } else {
            tEnd = T;
        }

        for (; t < tEnd; t++) {
            asm volatile("cp.async.wait_group %0;" :: "n"(S - 2));
            __syncthreads();   // publishes slot t%S AND guards slot (t-1)%S rewrite
            if (t + S - 1 < T) stage(t + S - 1, (t + S - 1) % S);
            else asm volatile("cp.async.commit_group;" ::: "memory");

            const uint32_t stg = sb + (uint32_t)((t % S) * STGH) * 2u;
#pragma unroll
            for (int kk = 0; kk < 2; kk++) {
                uint32_t af[MT][4], bf[NP][4];
#pragma unroll
                for (int mt = 0; mt < MT; mt++) {
                    ldm4(af[mt], stg + aoff + (uint32_t)(mt * 16 * 80) + kk * 32u);
                    if (FUSEA) {
                        af[mt][0] = hmul2u(af[mt][0], attv[mt][0]);
                        af[mt][2] = hmul2u(af[mt][2], attv[mt][0]);
                        af[mt][1] = hmul2u(af[mt][1], attv[mt][1]);
                        af[mt][3] = hmul2u(af[mt][3], attv[mt][1]);
                    }
                }
#pragma unroll
                for (int p = 0; p < NP; p++)
                    ldm4(bf[p], stg + boff + (uint32_t)(p * 16 * 80) + kk * 32u);
#pragma unroll
                for (int mt = 0; mt < MT; mt++)
#pragma unroll
                    for (int nt = 0; nt < NT; nt++)
                        mma16(c[mt][nt], af[mt], &bf[nt >> 1][(nt & 1) * 2]);
            }
        }
    }

#pragma unroll
    for (int mt = 0; mt < MT; mt++) {
#pragma unroll
        for (int nt = 0; nt < NT; nt++) {
            int row = m0 + wm * (BM / 4) + mt * 16 + grp;
            int col = n0 + wn * (BN / 4) + nt * 8 + qid * 2;
            float v0 = c[mt][nt][0], v1 = c[mt][nt][1];
            float v2 = c[mt][nt][2], v3 = c[mt][nt][3];
            if (bias) {
                float u0 = bias[col], u1 = bias[col + 1];
                v0 += u0; v1 += u1; v2 += u0; v3 += u1;
            }
            if (ACT == 1) {
                v0 = fmaxf(v0, 0.0f); v1 = fmaxf(v1, 0.0f);
                v2 = fmaxf(v2, 0.0f); v3 = fmaxf(v3, 0.0f);
            }
            if (OUTH) {
                __half* Ch = (__half*)Cv;
                *(__half2*)(&Ch[(size_t)row * N + col])       = __floats2half2_rn(v0, v1);
                *(__half2*)(&Ch[(size_t)(row + 8) * N + col]) = __floats2half2_rn(v2, v3);
            } else {
                float* Cf = (float*)Cv + (size_t)bz * M * N;
                *(float2*)(&Cf[(size_t)row * N + col])       = make_float2(v0, v1);
                *(float2*)(&Cf[(size_t)(row + 8) * N + col]) = make_float2(v2, v3);
            }
        }
    }
}

template <int BM, int BN, int ACT, int OUTH>
__global__ void __launch_bounds__(512, 1)
hgemm(const __half* __restrict__ A, const __half* __restrict__ W,
      const float* __restrict__ bias, void* __restrict__ Cv,
      int M, int N, int K, int kChunk) {
    extern __shared__ __align__(16) __half sm[];
    gemm_body<BM, BN, ACT, OUTH, 0>(sm, blockIdx.x, blockIdx.y, blockIdx.z,
                                    A, W, bias, Cv, M, N, K, kChunk, nullptr);
}

// G1: fused rtrans + bias, split-K=4
__global__ void __launch_bounds__(512, 1)
g1_kernel(const __half* __restrict__ eh2, const __half* __restrict__ WT,
          float* __restrict__ rt, const __half* __restrict__ atth) {
    extern __shared__ __align__(16) __half sm[];
    gemm_body<128, 256, 0, 0, 1>(sm, blockIdx.x, blockIdx.y, blockIdx.z,
                                 eh2, WT, nullptr, rt, BB, D2C, KBIG2, KBIG2 / G1Z, atth);
}

// ln_rtrans: sum split-K partials + LN (one batch row per block)
__global__ void __launch_bounds__(512, 1)
lnr_kernel() {
    __shared__ float red[512];
    int b = blockIdx.x, t = threadIdx.x;
    float v[2], s = 0.0f;
#pragma unroll
    for (int u = 0; u < 2; u++) {
        int i = t + u * 512;
        float x = 0.0f;
#pragma unroll
        for (int z = 0; z < G1Z; z++) x += g_rt[((size_t)z * BB + b) * D2C + i];
        v[u] = x; s += x;
    }
    red[t] = s; __syncthreads();
#pragma unroll
    for (int st = 256; st > 0; st >>= 1) { if (t < st) red[t] += red[t + st]; __syncthreads(); }
    float mean = red[0] * (1.0f / D2C); __syncthreads();
    float d = 0.0f;
#pragma unroll
    for (int u = 0; u < 2; u++) { float dv = v[u] - mean; d += dv * dv; }
    red[t] = d; __syncthreads();
#pragma unroll
    for (int st = 256; st > 0; st >>= 1) { if (t < st) red[t] += red[t + st]; __syncthreads(); }
    float inv = rsqrtf(red[0] * (1.0f / D2C) + LN_EPS_F);
#pragma unroll
    for (int u = 0; u < 2; u++)
        g_xstack[b * D2C + t + u * 512] = __float2half_rn((v[u] - mean) * inv);
}

// G6 + fuse
__global__ void __launch_bounds__(512, 1)
g6fuse_kernel(const __half* __restrict__ A, const __half* __restrict__ W,
              const float* __restrict__ ba2, float* __restrict__ out) {
    constexpr int S = 4;
    constexpr int STGH = 256 * 40;
    extern __shared__ __align__(16) __half sm[];
    const uint32_t sb = smem_u32(sm);
    const int tid = threadIdx.x, lane = tid & 31, wid = tid >> 5;
    const int wm = wid & 3, wn = wid >> 2;
    const int grp = lane >> 2, qid = lane & 3;
    const int g = lane >> 3, lr = lane & 7;
    const int m0 = blockIdx.y * 64, n0 = blockIdx.x * 128;
    const int T = DIMC / 32;

    const uint32_t a0off = (uint32_t)(wm * 16 + (g & 1) * 8 + lr) * 80u + (g >> 1) * 16u;
    const uint32_t a1off = a0off + 64u * 80u;
    const uint32_t boff  = (uint32_t)(128 + wn * 32 + (g >> 1) * 8 + lr) * 80u + (g & 1) * 16u;

    float c0[4][4], c1[4][4];
#pragma unroll
    for (int j = 0; j < 4; j++)
#pragma unroll
        for (int q = 0; q < 4; q++) { c0[j][q] = 0.0f; c1[j][q] = 0.0f; }

    auto stage = [&](int t, int s) {
        uint32_t base = sb + (uint32_t)(s * STGH) * 2u;
        const __half* A0 = A + (size_t)m0 * DIMC + t * 32;
        const __half* A1 = A + (size_t)(BB + m0) * DIMC + t * 32;
        const __half* Wp = W + (size_t)n0 * DIMC + t * 32;
#pragma unroll
        for (int c2 = tid; c2 < 64 * 4; c2 += 512) {
            int row = c2 >> 2, q = c2 & 3;
            cp16(base + (uint32_t)(row * 80 + q * 16), A0 + (size_t)row * DIMC + q * 8);
            cp16(base + (uint32_t)((row + 64) * 80 + q * 16), A1 + (size_t)row * DIMC + q * 8);
        }
#pragma unroll
        for (int c2 = tid; c2 < 128 * 4; c2 += 512) {
            int row = c2 >> 2, q = c2 & 3;
            cp16(base + (uint32_t)((row + 128) * 80 + q * 16), Wp + (size_t)row * DIMC + q * 8);
        }
        asm volatile("cp.async.commit_group;" ::: "memory");
    };

    for (int u = 0; u < S - 1 && u < T; u++) stage(u, u);

    for (int t = 0; t < T; t++) {
        asm volatile("cp.async.wait_group %0;" :: "n"(S - 2));
        __syncthreads();
        if (t + S - 1 < T) stage(t + S - 1, (t + S - 1) % S);
        else asm volatile("cp.async.commit_group;" ::: "memory");

        const uint32_t stg = sb + (uint32_t)((t % S) * STGH) * 2u;
#pragma unroll
        for (int kk = 0; kk < 2; kk++) {
            uint32_t a0f[4], a1f[4], bf[2][4];
            ldm4(a0f, stg + a0off + kk * 32u);
            ldm4(a1f, stg + a1off + kk * 32u);
#pragma unroll
            for (int p = 0; p < 2; p++)
                ldm4(bf[p], stg + boff + (uint32_t)(p * 16 * 80) + kk * 32u);
#pragma unroll
            for (int nt = 0; nt < 4; nt++) {
                mma16(c0[nt], a0f, &bf[nt >> 1][(nt & 1) * 2]);
                mma16(c1[nt], a1f, &bf[nt >> 1][(nt & 1) * 2]);
            }
        }
    }

#pragma unroll
    for (int nt = 0; nt < 4; nt++) {
        int row = m0 + wm * 16 + grp;
        int col = n0 + wn * 32 + nt * 8 + qid * 2;
        float u0 = ba2[col], u1 = ba2[col + 1];
#pragma unroll
        for (int half = 0; half < 2; half++) {
            int r = row + half * 8;
            float s0a = c0[nt][half * 2] + u0, s0b = c0[nt][half * 2 + 1] + u1;
            float s1a = c1[nt][half * 2] + u0, s1b = c1[nt][half * 2 + 1] + u1;
            __half2 xr = *(const __half2*)&g_xstack[(size_t)r * D2C + col];
            __half2 xm = *(const __half2*)&g_xstack[(size_t)(BB + r) * D2C + col];
            float pa = 1.0f / (1.0f + expf(s1a - s0a));
            float pb = 1.0f / (1.0f + expf(s1b - s0b));
            float xa = pa * __low2float(xr) + (1.0f - pa) * __low2float(xm);
            float xb = pb * __high2float(xr) + (1.0f - pb) * __high2float(xm);
            float2 o;
            if (col < DIMC) {
                o.x = tanhf(xa) * PI_F;
                o.y = tanhf(xb) * PI_F;
                *(float2*)&out[(size_t)r * DIMC + col] = o;
            } else {
                o.x = tanhf(2.0f * xa) * (PI_F * 0.5f) + (PI_F * 0.5f);
                o.y = tanhf(2.0f * xb) * (PI_F * 0.5f) + (PI_F * 0.5f);
                *(float2*)&out[(size_t)BB * DIMC + (size_t)r * DIMC + (col - DIMC)] = o;
            }
        }
    }
}

// front kernel: transpose + rel_bias^T + prep + weight copies
#define NTR ((KBIG / 32) * (D2C / 64))
#define NBI 120
#define NPR BB
__global__ void front_kernel(const float* __restrict__ rb, const float* __restrict__ rel_bias,
                             const float* __restrict__ ax, const float* __restrict__ ag,
                             const int* __restrict__ idx, const float* __restrict__ rel_att,
                             const float* __restrict__ rax, const float* __restrict__ rag,
                             const float* s1, __half* d1, int n1,
                             const float* s2, __half* d2, int n2,
                             const float* s3, __half* d3, int n3,
                             const float* s4, __half* d4, int n4,
                             const float* s5, __half* d5, int n5) {
    int bid = blockIdx.x, t = threadIdx.x;
    if (bid < NTR) {
        __shared__ float tile[32][67];
        int k0 = (bid % (KBIG / 32)) * 32, n0 = (bid / (KBIG / 32)) * 64;
#pragma unroll
        for (int i = 0; i < 2; i++) {
            int idx2 = t + i * 256;
            int row = idx2 >> 4, c4 = idx2 & 15;
            float4 v = *(const float4*)&rb[(size_t)(k0 + row) * D2C + n0 + c4 * 4];
            tile[row][c4 * 4 + 0] = v.x; tile[row][c4 * 4 + 1] = v.y;
            tile[row][c4 * 4 + 2] = v.z; tile[row][c4 * 4 + 3] = v.w;
        }
        __syncthreads();
        int n = t >> 2, kg = t & 3;
        __half hv[8];
#pragma unroll
        for (int j = 0; j < 8; j++) hv[j] = __float2half_rn(tile[kg * 8 + j][n]);
        *(uint4*)&g_WT[(size_t)(n0 + n) * KBIG2 + k0 + kg * 8] = *(uint4*)hv;
        return;
    }
    bid -= NTR;
    if (bid < NBI) {
        int idx2 = bid * 256 + t;
        if (idx2 < 30720) {
            int n = idx2 / 30, j = idx2 % 30;
            g_WT[(size_t)n * KBIG2 + KBIG + j] = __float2half_rn(rel_bias[j * D2C + n]);
        }
        return;
    }
    bid -= NBI;
    if (bid < NPR) {
        int b = bid;
        int rid = idx[b];
        if (t < 32) {
            float v = (t < NBASE) ? tanhf(rel_att[rid * NBASE + t] * INV_EMB) * PI_F : 0.0f;
            g_atth[b * 32 + t] = (t < NBASE) ? __float2half_rn(v) :
                                 (t == 30 ? __float2half_rn(1.0f) : __float2half_rn(0.0f));
            g_eh2[b * 2048 + 1024 + t] = __float2half_rn(v);
        }
        for (int j = t; j < DIMC; j += 256) {
            float a = ax[b * DIMC + j], g = ag[b * DIMC + j];
            g_eh2[b * 2048 + j]        = __float2half_rn(a);
            g_eh2[b * 2048 + DIMC + j] = __float2half_rn(g);
            float rx = tanhf(rax[rid * DIMC + j] * INV_EMB) * PI_F;
            float rg = tanhf(2.0f * (rag[rid * DIMC + j] * INV_EMB)) * (PI_F * 0.5f) + (PI_F * 0.5f);
            g_hin[b * D2C + j] = __float2half_rn(a + rx);
            g_hin[b * D2C + DIMC + j] = __float2half_rn(g + rg);
        }
        return;
    }
    bid -= NPR;
    int i = bid * 256 + t;
    const float* s; __half* d; int off = i;
    if (off < n1) { s = s1; d = d1; }
    else if ((off -= n1) < n2) { s = s2; d = d2; }
    else if ((off -= n2) < n3) { s = s3; d = d3; }
    else if ((off -= n3) < n4) { s = s4; d = d4; }
    else if ((off -= n4) < n5) { s = s5; d = d5; }
    else return;
    float4 v = ((const float4*)s)[off];
    __half2* dd = (__half2*)d;
    dd[off * 2]     = __floats2half2_rn(v.x, v.y);
    dd[off * 2 + 1] = __floats2half2_rn(v.z, v.w);
}

__device__ __forceinline__ float block_sum(float v, float* red) {
    int t = threadIdx.x;
    red[t] = v; __syncthreads();
#pragma unroll
    for (int s = 128; s > 0; s >>= 1) { if (t < s) red[t] += red[t + s]; __syncthreads(); }
    float r = red[0]; __syncthreads();
    return r;
}

__global__ void ln_mlp_kernel(const float* __restrict__ b0) {
    __shared__ float red[256];
    int b = blockIdx.x, t = threadIdx.x;
    float v[4], s = 0.0f;
#pragma unroll
    for (int u = 0; u < 4; u++) {
        int i = t + u * 256;
        v[u] = g_x0[b * D2C + i] + g_x0[(size_t)(BB + b) * D2C + i] + b0[i];
        s += v[u];
    }
    float mean = block_sum(s, red) * (1.0f / D2C);
    float d = 0.0f;
#pragma unroll
    for (int u = 0; u < 4; u++) { float dv = v[u] - mean; d += dv * dv; }
    float inv = rsqrtf(block_sum(d, red) * (1.0f / D2C) + LN_EPS_F);
#pragma unroll
    for (int u = 0; u < 4; u++)
        g_xstack[(size_t)(BB + b) * D2C + t + u * 256] = __float2half_rn((v[u] - mean) * inv);
}

extern "C" void kernel_launch(void* const* d_in, const int* in_sizes, int n_in,
                              void* d_out, int out_size) {
    const float* ax = (const float*)d_in[0];
    const float* ag = (const float*)d_in[1];
    const int* idx = (const int*)d_in[2];
    const float* rel_base = (const float*)d_in[3];
    const float* rel_att = (const float*)d_in[4];
    const float* rel_bias = (const float*)d_in[5];
    const float* rax = (const float*)d_in[6];
    const float* rag = (const float*)d_in[7];
    const float* W1 = (const float*)d_in[8];
    const float* b1 = (const float*)d_in[9];
    const float* W2 = (const float*)d_in[10];
    const float* b2 = (const float*)d_in[11];
    const float* W0 = (const float*)d_in[12];
    const float* b0 = (const float*)d_in[13];
    const float* Wa1 = (const float*)d_in[14];
    const float* ba1 = (const float*)d_in[15];
    const float* Wa2 = (const float*)d_in[16];
    const float* ba2 = (const float*)d_in[17];
    float* out = (float*)d_out;

    __half *pWT, *peh2, *path, *phin, *ph1, *ph2, *pxs, *pa;
    __half *pw1, *pw2, *pw0, *pwa1, *pwa2;
    float *prt, *px0;
    cudaGetSymbolAddress((void**)&pWT, g_WT);
    cudaGetSymbolAddress((void**)&peh2, g_eh2);
    cudaGetSymbolAddress((void**)&path, g_atth);
    cudaGetSymbolAddress((void**)&phin, g_hin);
    cudaGetSymbolAddress((void**)&ph1, g_h1);
    cudaGetSymbolAddress((void**)&ph2, g_h2);
    cudaGetSymbolAddress((void**)&pxs, g_xstack);
    cudaGetSymbolAddress((void**)&pa, g_a);
    cudaGetSymbolAddress((void**)&prt, g_rt);
    cudaGetSymbolAddress((void**)&px0, g_x0);
    cudaGetSymbolAddress((void**)&pw1, g_w1h);
    cudaGetSymbolAddress((void**)&pw2, g_w2h);
    cudaGetSymbolAddress((void**)&pw0, g_w0h);
    cudaGetSymbolAddress((void**)&pwa1, g_wa1h);
    cudaGetSymbolAddress((void**)&pwa2, g_wa2h);

    const int SMB256 = 4 * (128 + 256) * 40 * 2;  // 122880
    const int SMB128 = 4 * (128 + 128) * 40 * 2;  // 81920
    const int SMB64  = 4 * (64 + 128) * 40 * 2;   // 61440
    const int SMG6   = 4 * 256 * 40 * 2;          // 81920
    cudaFuncSetAttribute(g1_kernel,
                         cudaFuncAttributeMaxDynamicSharedMemorySize, SMB256);
    cudaFuncSetAttribute(hgemm<128, 128, 0, 0>,
                         cudaFuncAttributeMaxDynamicSharedMemorySize, SMB128);
    cudaFuncSetAttribute(hgemm<128, 128, 1, 1>,
                         cudaFuncAttributeMaxDynamicSharedMemorySize, SMB128);
    cudaFuncSetAttribute(hgemm<64, 128, 1, 1>,
                         cudaFuncAttributeMaxDynamicSharedMemorySize, SMB64);
    cudaFuncSetAttribute(g6fuse_kernel,
                         cudaFuncAttributeMaxDynamicSharedMemorySize, SMG6);

    // side stream + fork/join events (created once; host objects, no device mem)
    static cudaStream_t s2 = nullptr;
    static cudaEvent_t evFork = nullptr, evJoin = nullptr;
    if (!s2) {
        cudaStreamCreateWithFlags(&s2, cudaStreamNonBlocking);
        cudaEventCreateWithFlags(&evFork, cudaEventDisableTiming);
        cudaEventCreateWithFlags(&evJoin, cudaEventDisableTiming);
    }

    int n1 = HIDC * D2C / 4, n2 = HIDC * HIDC / 4, n3 = D2C * HIDC / 4;
    int n4 = DIMC * D2C / 4, n5 = D2C * DIMC / 4;
    int ncopy = (n1 + n2 + n3 + n4 + n5 + 255) / 256;
    front_kernel<<<NTR + NBI + NPR + ncopy, 256>>>(
        rel_base, rel_bias, ax, ag, idx, rel_att, rax, rag,
        W1, pw1, n1, W2, pw2, n2, W0, pw0, n3, Wa1, pwa1, n4, Wa2, pwa2, n5);

    // fork: branch B (MLP chain) on side stream
    cudaEventRecord(evFork, 0);
    cudaStreamWaitEvent(s2, evFork, 0);

    // branch B: G2 -> G3 -> G4 -> ln_mlp -> G5b
    hgemm<128, 128, 1, 1><<<dim3(HIDC / 128, BB / 128, 1), 512, SMB128, s2>>>(
        phin, pw1, b1, ph1, BB, HIDC, D2C, D2C);
    hgemm<128, 128, 1, 1><<<dim3(HIDC / 128, BB / 128, 1), 512, SMB128, s2>>>(
        ph1, pw2, b2, ph2, BB, HIDC, HIDC, HIDC);
    hgemm<128, 128, 0, 0><<<dim3(D2C / 128, BB / 128, 2), 512, SMB128, s2>>>(
        ph2, pw0, nullptr, px0, BB, D2C, HIDC, HIDC / 2);
    ln_mlp_kernel<<<BB, 256, 0, s2>>>(b0);
    hgemm<64, 128, 1, 1><<<dim3(DIMC / 128, BB / 64, 1), 512, SMB64, s2>>>(
        pxs + (size_t)BB * D2C, pwa1, ba1, pa + (size_t)BB * DIMC, BB, DIMC, D2C, D2C);
    cudaEventRecord(evJoin, s2);

    // branch A (main stream): G1 -> ln_rtrans -> G5a
    g1_kernel<<<dim3(D2C / 256, BB / 128, G1Z), 512, SMB256>>>(peh2, pWT, prt, path);
    lnr_kernel<<<BB, 512>>>();
    hgemm<64, 128, 1, 1><<<dim3(DIMC / 128, BB / 64, 1), 512, SMB64>>>(
        pxs, pwa1, ba1, pa, BB, DIMC, D2C, D2C);

    // join, then G6 + fuse
    cudaStreamWaitEvent(0, evJoin, 0);
    g6fuse_kernel<<<dim3(D2C / 128, BB / 64), 512, SMG6>>>(pa, pwa2, ba2, out);
}

// round 16
// speedup vs baseline: 1.1181x; 1.0016x over previous
#include <cuda_runtime.h>
#include <cuda_fp16.h>
#include <math.h>
#include <stdint.h>

#define BB    1024
#define DIMC  512
#define D2C   1024
#define HIDC  2048
#define NBASE 30
#define KBIG  (NBASE * D2C)     // 30720
#define KBIG2 (KBIG + 1024)     // 31744 (incl. bias block r=30)
#define G1Z   4

#define PI_F      3.14159265358979323846f
#define INV_EMB   36.3636363636363636f
#define LN_EPS_F  1e-5f

__device__ __half g_atth[BB * 32];
__device__ __half g_eh2[BB * 2048];
__device__ __half g_hin[BB * D2C];
__device__ __half g_WT[(size_t)D2C * KBIG2];
__device__ float  g_rt[(size_t)G1Z * BB * D2C];
__device__ __half g_h1[BB * HIDC];
__device__ __half g_h2[BB * HIDC];
__device__ float  g_x0[2 * BB * D2C];
__device__ __half g_xstack[2 * BB * D2C];
__device__ __half g_a[2 * BB * DIMC];
__device__ __half g_w1h[HIDC * D2C];
__device__ __half g_w2h[HIDC * HIDC];
__device__ __half g_w0h[D2C * HIDC];
__device__ __half g_wa1h[DIMC * D2C];
__device__ __half g_wa2h[D2C * DIMC];

__device__ __forceinline__ uint32_t smem_u32(const void* p) {
    uint32_t a;
    asm("{ .reg .u64 t; cvta.to.shared.u64 t, %1; cvt.u32.u64 %0, t; }" : "=r"(a) : "l"(p));
    return a;
}
__device__ __forceinline__ void cp16(uint32_t d, const void* s) {
    asm volatile("cp.async.cg.shared.global [%0], [%1], 16;" :: "r"(d), "l"(s) : "memory");
}
__device__ __forceinline__ void ldm4(uint32_t* r, uint32_t addr) {
    asm volatile("ldmatrix.sync.aligned.m8n8.x4.shared.b16 {%0,%1,%2,%3}, [%4];"
                 : "=r"(r[0]), "=r"(r[1]), "=r"(r[2]), "=r"(r[3]) : "r"(addr));
}
__device__ __forceinline__ void mma16(float* c, const uint32_t* a, const uint32_t* b) {
    asm volatile(
        "mma.sync.aligned.m16n8k16.row.col.f32.f16.f16.f32 "
        "{%0,%1,%2,%3},{%4,%5,%6,%7},{%8,%9},{%0,%1,%2,%3};"
        : "+f"(c[0]), "+f"(c[1]), "+f"(c[2]), "+f"(c[3])
        : "r"(a[0]), "r"(a[1]), "r"(a[2]), "r"(a[3]), "r"(b[0]), "r"(b[1]));
}
__device__ __forceinline__ uint32_t hmul2u(uint32_t a, __half2 s) {
    __half2 r = __hmul2(*(__half2*)&a, s);
    return *(uint32_t*)&r;
}

// fp16 HMMA GEMM body, 512 threads = 16 warps (4M x 4N), one sync/iter.
template <int BM, int BN, int ACT, int OUTH, int FUSEA>
__device__ __forceinline__ void gemm_body(
    __half* sm, int bx, int by, int bz,
    const __half* __restrict__ A, const __half* __restrict__ W,
    const float* __restrict__ bias, void* __restrict__ Cv,
    int M, int N, int K, int kChunk, const __half* __restrict__ atth) {
    constexpr int S    = 4;
    constexpr int MT   = BM / 64;
    constexpr int NT   = BN / 32;
    constexpr int NP   = NT / 2;
    constexpr int STGH = (BM + BN) * 40;

    const uint32_t sb = smem_u32(sm);
    const int tid = threadIdx.x, lane = tid & 31, wid = tid >> 5;
    const int wm = wid & 3, wn = wid >> 2;
    const int grp = lane >> 2, qid = lane & 3;
    const int g = lane >> 3, lr = lane & 7;
    const int m0 = by * BM, n0 = bx * BN;
    const int kStart = bz * kChunk;
    const int T = kChunk / 32;

    const uint32_t aoff = (uint32_t)(wm * (BM / 4) + (g & 1) * 8 + lr) * 80u + (g >> 1) * 16u;
    const uint32_t boff = (uint32_t)(BM + wn * (BN / 4) + (g >> 1) * 8 + lr) * 80u + (g & 1) * 16u;

    float c[MT][NT][4];
#pragma unroll
    for (int i = 0; i < MT; i++)
#pragma unroll
        for (int j = 0; j < NT; j++)
#pragma unroll
            for (int q = 0; q < 4; q++) c[i][j][q] = 0.0f;

    auto stage = [&](int t, int s) {
        uint32_t base = sb + (uint32_t)(s * STGH) * 2u;
        const __half* Ap;
        size_t astr;
        if (FUSEA) {
            int k = kStart + t * 32;
            Ap = A + (size_t)m0 * 2048 + ((k >= KBIG) ? 1024 : 0) + (k & 1023);
            astr = 2048;
        } else {
            Ap = A + (size_t)m0 * K + kStart + t * 32;
            astr = K;
        }
        const __half* Wp = W + (size_t)n0 * K + kStart + t * 32;
#pragma unroll
        for (int c2 = tid; c2 < BM * 4; c2 += 512) {
            int row = c2 >> 2, q = c2 & 3;
            cp16(base + (uint32_t)(row * 80 + q * 16), Ap + (size_t)row * astr + q * 8);
        }
#pragma unroll
        for (int c2 = tid; c2 < BN * 4; c2 += 512) {
            int row = c2 >> 2, q = c2 & 3;
            cp16(base + (uint32_t)(BM * 80 + row * 80 + q * 16), Wp + (size_t)row * K + q * 8);
        }
        asm volatile("cp.async.commit_group;" ::: "memory");
    };

    for (int u = 0; u < S - 1 && u < T; u++) stage(u, u);

    int t = 0;
    while (t < T) {
        __half2 attv[MT][2];
        int tEnd;
        if (FUSEA) {
            int r = (kStart + (t << 5)) >> 10;
#pragma unroll
            for (int mt = 0; mt < MT; mt++) {
                int rowA = m0 + wm * (BM / 4) + mt * 16 + grp;
                attv[mt][0] = __half2half2(atth[rowA * 32 + r]);
                attv[mt][1] = __half2half2(atth[(rowA + 8) * 32 + r]);
            }
            int tNext = (((r + 1) << 10) - kStart) >> 5;
            tEnd = tNext < T ? tNext : T;
        } else {
            tEnd = T;
        }

        for (; t < tEnd; t++) {
            asm volatile("cp.async.wait_group %0;" :: "n"(S - 2));
            __syncthreads();
            if (t + S - 1 < T) stage(t + S - 1, (t + S - 1) % S);
            else asm volatile("cp.async.commit_group;" ::: "memory");

            const uint32_t stg = sb + (uint32_t)((t % S) * STGH) * 2u;
#pragma unroll
            for (int kk = 0; kk < 2; kk++) {
                uint32_t af[MT][4], bf[NP][4];
#pragma unroll
                for (int mt = 0; mt < MT; mt++) {
                    ldm4(af[mt], stg + aoff + (uint32_t)(mt * 16 * 80) + kk * 32u);
                    if (FUSEA) {
                        af[mt][0] = hmul2u(af[mt][0], attv[mt][0]);
                        af[mt][2] = hmul2u(af[mt][2], attv[mt][0]);
                        af[mt][1] = hmul2u(af[mt][1], attv[mt][1]);
                        af[mt][3] = hmul2u(af[mt][3], attv[mt][1]);
                    }
                }
#pragma unroll
                for (int p = 0; p < NP; p++)
                    ldm4(bf[p], stg + boff + (uint32_t)(p * 16 * 80) + kk * 32u);
#pragma unroll
                for (int mt = 0; mt < MT; mt++)
#pragma unroll
                    for (int nt = 0; nt < NT; nt++)
                        mma16(c[mt][nt], af[mt], &bf[nt >> 1][(nt & 1) * 2]);
            }
        }
    }

#pragma unroll
    for (int mt = 0; mt < MT; mt++) {
#pragma unroll
        for (int nt = 0; nt < NT; nt++) {
            int row = m0 + wm * (BM / 4) + mt * 16 + grp;
            int col = n0 + wn * (BN / 4) + nt * 8 + qid * 2;
            float v0 = c[mt][nt][0], v1 = c[mt][nt][1];
            float v2 = c[mt][nt][2], v3 = c[mt][nt][3];
            if (bias) {
                float u0 = bias[col], u1 = bias[col + 1];
                v0 += u0; v1 += u1; v2 += u0; v3 += u1;
            }
            if (ACT == 1) {
                v0 = fmaxf(v0, 0.0f); v1 = fmaxf(v1, 0.0f);
                v2 = fmaxf(v2, 0.0f); v3 = fmaxf(v3, 0.0f);
            }
            if (OUTH) {
                __half* Ch = (__half*)Cv;
                *(__half2*)(&Ch[(size_t)row * N + col])       = __floats2half2_rn(v0, v1);
                *(__half2*)(&Ch[(size_t)(row + 8) * N + col]) = __floats2half2_rn(v2, v3);
            } else {
                float* Cf = (float*)Cv + (size_t)bz * M * N;
                *(float2*)(&Cf[(size_t)row * N + col])       = make_float2(v0, v1);
                *(float2*)(&Cf[(size_t)(row + 8) * N + col]) = make_float2(v2, v3);
            }
        }
    }
}

template <int BM, int BN, int ACT, int OUTH>
__global__ void __launch_bounds__(512, 1)
hgemm(const __half* __restrict__ A, const __half* __restrict__ W,
      const float* __restrict__ bias, void* __restrict__ Cv,
      int M, int N, int K, int kChunk) {
    extern __shared__ __align__(16) __half sm[];
    gemm_body<BM, BN, ACT, OUTH, 0>(sm, blockIdx.x, blockIdx.y, blockIdx.z,
                                    A, W, bias, Cv, M, N, K, kChunk, nullptr);
}

// G1: fused rtrans + bias, split-K=4
__global__ void __launch_bounds__(512, 1)
g1_kernel(const __half* __restrict__ eh2, const __half* __restrict__ WT,
          float* __restrict__ rt, const __half* __restrict__ atth) {
    extern __shared__ __align__(16) __half sm[];
    gemm_body<128, 256, 0, 0, 1>(sm, blockIdx.x, blockIdx.y, blockIdx.z,
                                 eh2, WT, nullptr, rt, BB, D2C, KBIG2, KBIG2 / G1Z, atth);
}

// ln_rtrans: sum split-K partials + LN
__global__ void __launch_bounds__(512, 1)
lnr_kernel() {
    __shared__ float red[512];
    int b = blockIdx.x, t = threadIdx.x;
    float v[2], s = 0.0f;
#pragma unroll
    for (int u = 0; u < 2; u++) {
        int i = t + u * 512;
        float x = 0.0f;
#pragma unroll
        for (int z = 0; z < G1Z; z++) x += g_rt[((size_t)z * BB + b) * D2C + i];
        v[u] = x; s += x;
    }
    red[t] = s; __syncthreads();
#pragma unroll
    for (int st = 256; st > 0; st >>= 1) { if (t < st) red[t] += red[t + st]; __syncthreads(); }
    float mean = red[0] * (1.0f / D2C); __syncthreads();
    float d = 0.0f;
#pragma unroll
    for (int u = 0; u < 2; u++) { float dv = v[u] - mean; d += dv * dv; }
    red[t] = d; __syncthreads();
#pragma unroll
    for (int st = 256; st > 0; st >>= 1) { if (t < st) red[t] += red[t + st]; __syncthreads(); }
    float inv = rsqrtf(red[0] * (1.0f / D2C) + LN_EPS_F);
#pragma unroll
    for (int u = 0; u < 2; u++)
        g_xstack[b * D2C + t + u * 512] = __float2half_rn((v[u] - mean) * inv);
}

// G6 + fuse
__global__ void __launch_bounds__(512, 1)
g6fuse_kernel(const __half* __restrict__ A, const __half* __restrict__ W,
              const float* __restrict__ ba2, float* __restrict__ out) {
    constexpr int S = 4;
    constexpr int STGH = 256 * 40;
    extern __shared__ __align__(16) __half sm[];
    const uint32_t sb = smem_u32(sm);
    const int tid = threadIdx.x, lane = tid & 31, wid = tid >> 5;
    const int wm = wid & 3, wn = wid >> 2;
    const int grp = lane >> 2, qid = lane & 3;
    const int g = lane >> 3, lr = lane & 7;
    const int m0 = blockIdx.y * 64, n0 = blockIdx.x * 128;
    const int T = DIMC / 32;

    const uint32_t a0off = (uint32_t)(wm * 16 + (g & 1) * 8 + lr) * 80u + (g >> 1) * 16u;
    const uint32_t a1off = a0off + 64u * 80u;
    const uint32_t boff  = (uint32_t)(128 + wn * 32 + (g >> 1) * 8 + lr) * 80u + (g & 1) * 16u;

    float c0[4][4], c1[4][4];
#pragma unroll
    for (int j = 0; j < 4; j++)
#pragma unroll
        for (int q = 0; q < 4; q++) { c0[j][q] = 0.0f; c1[j][q] = 0.0f; }

    auto stage = [&](int t, int s) {
        uint32_t base = sb + (uint32_t)(s * STGH) * 2u;
        const __half* A0 = A + (size_t)m0 * DIMC + t * 32;
        const __half* A1 = A + (size_t)(BB + m0) * DIMC + t * 32;
        const __half* Wp = W + (size_t)n0 * DIMC + t * 32;
#pragma unroll
        for (int c2 = tid; c2 < 64 * 4; c2 += 512) {
            int row = c2 >> 2, q = c2 & 3;
            cp16(base + (uint32_t)(row * 80 + q * 16), A0 + (size_t)row * DIMC + q * 8);
            cp16(base + (uint32_t)((row + 64) * 80 + q * 16), A1 + (size_t)row * DIMC + q * 8);
        }
#pragma unroll
        for (int c2 = tid; c2 < 128 * 4; c2 += 512) {
            int row = c2 >> 2, q = c2 & 3;
            cp16(base + (uint32_t)((row + 128) * 80 + q * 16), Wp + (size_t)row * DIMC + q * 8);
        }
        asm volatile("cp.async.commit_group;" ::: "memory");
    };

    for (int u = 0; u < S - 1 && u < T; u++) stage(u, u);

    for (int t = 0; t < T; t++) {
        asm volatile("cp.async.wait_group %0;" :: "n"(S - 2));
        __syncthreads();
        if (t + S - 1 < T) stage(t + S - 1, (t + S - 1) % S);
        else asm volatile("cp.async.commit_group;" ::: "memory");

        const uint32_t stg = sb + (uint32_t)((t % S) * STGH) * 2u;
#pragma unroll
        for (int kk = 0; kk < 2; kk++) {
            uint32_t a0f[4], a1f[4], bf[2][4];
            ldm4(a0f, stg + a0off + kk * 32u);
            ldm4(a1f, stg + a1off + kk * 32u);
#pragma unroll
            for (int p = 0; p < 2; p++)
                ldm4(bf[p], stg + boff + (uint32_t)(p * 16 * 80) + kk * 32u);
#pragma unroll
            for (int nt = 0; nt < 4; nt++) {
                mma16(c0[nt], a0f, &bf[nt >> 1][(nt & 1) * 2]);
                mma16(c1[nt], a1f, &bf[nt >> 1][(nt & 1) * 2]);
            }
        }
    }

#pragma unroll
    for (int nt = 0; nt < 4; nt++) {
        int row = m0 + wm * 16 + grp;
        int col = n0 + wn * 32 + nt * 8 + qid * 2;
        float u0 = ba2[col], u1 = ba2[col + 1];
#pragma unroll
        for (int half = 0; half < 2; half++) {
            int r = row + half * 8;
            float s0a = c0[nt][half * 2] + u0, s0b = c0[nt][half * 2 + 1] + u1;
            float s1a = c1[nt][half * 2] + u0, s1b = c1[nt][half * 2 + 1] + u1;
            __half2 xr = *(const __half2*)&g_xstack[(size_t)r * D2C + col];
            __half2 xm = *(const __half2*)&g_xstack[(size_t)(BB + r) * D2C + col];
            float pa = 1.0f / (1.0f + expf(s1a - s0a));
            float pb = 1.0f / (1.0f + expf(s1b - s0b));
            float xa = pa * __low2float(xr) + (1.0f - pa) * __low2float(xm);
            float xb = pb * __high2float(xr) + (1.0f - pb) * __high2float(xm);
            float2 o;
            if (col < DIMC) {
                o.x = tanhf(xa) * PI_F;
                o.y = tanhf(xb) * PI_F;
                *(float2*)&out[(size_t)r * DIMC + col] = o;
            } else {
                o.x = tanhf(2.0f * xa) * (PI_F * 0.5f) + (PI_F * 0.5f);
                o.y = tanhf(2.0f * xb) * (PI_F * 0.5f) + (PI_F * 0.5f);
                *(float2*)&out[(size_t)BB * DIMC + (size_t)r * DIMC + (col - DIMC)] = o;
            }
        }
    }
}

// fp32->fp16 copy over up to 3 tensors (block-range)
__global__ void copy3_kernel(const float* s1, __half* d1, int n1,
                             const float* s2, __half* d2, int n2,
                             const float* s3, __half* d3, int n3) {
    int off = blockIdx.x * 256 + threadIdx.x;
    const float* s; __half* d;
    if (off < n1) { s = s1; d = d1; }
    else if ((off -= n1) < n2) { s = s2; d = d2; }
    else if ((off -= n2) < n3) { s = s3; d = d3; }
    else return;
    float4 v = ((const float4*)s)[off];
    __half2* dd = (__half2*)d;
    dd[off * 2]     = __floats2half2_rn(v.x, v.y);
    dd[off * 2 + 1] = __floats2half2_rn(v.z, v.w);
}

// front1: prep + wa1/wa2 copies (branch-A-side needs; pre-fork)
#define NPR BB
__global__ void front1_kernel(const float* __restrict__ ax, const float* __restrict__ ag,
                              const int* __restrict__ idx, const float* __restrict__ rel_att,
                              const float* __restrict__ rax, const float* __restrict__ rag,
                              const float* s4, __half* d4, int n4,
                              const float* s5, __half* d5, int n5) {
    int bid = blockIdx.x, t = threadIdx.x;
    if (bid < NPR) {
        int b = bid;
        int rid = idx[b];
        if (t < 32) {
            float v = (t < NBASE) ? tanhf(rel_att[rid * NBASE + t] * INV_EMB) * PI_F : 0.0f;
            g_atth[b * 32 + t] = (t < NBASE) ? __float2half_rn(v) :
                                 (t == 30 ? __float2half_rn(1.0f) : __float2half_rn(0.0f));
            g_eh2[b * 2048 + 1024 + t] = __float2half_rn(v);
        }
        for (int j = t; j < DIMC; j += 256) {
            float a = ax[b * DIMC + j], g = ag[b * DIMC + j];
            g_eh2[b * 2048 + j]        = __float2half_rn(a);
            g_eh2[b * 2048 + DIMC + j] = __float2half_rn(g);
            float rx = tanhf(rax[rid * DIMC + j] * INV_EMB) * PI_F;
            float rg = tanhf(2.0f * (rag[rid * DIMC + j] * INV_EMB)) * (PI_F * 0.5f) + (PI_F * 0.5f);
            g_hin[b * D2C + j] = __float2half_rn(a + rx);
            g_hin[b * D2C + DIMC + j] = __float2half_rn(g + rg);
        }
        return;
    }
    bid -= NPR;
    int off = bid * 256 + t;
    const float* s; __half* d;
    if (off < n4) { s = s4; d = d4; }
    else if ((off -= n4) < n5) { s = s5; d = d5; }
    else return;
    float4 v = ((const float4*)s)[off];
    __half2* dd = (__half2*)d;
    dd[off * 2]     = __floats2half2_rn(v.x, v.y);
    dd[off * 2 + 1] = __floats2half2_rn(v.z, v.w);
}

// front2: rel_base transpose + rel_bias^T (main stream, overlapped with branch B)
#define NTR ((KBIG / 32) * (D2C / 64))
#define NBI 120
__global__ void front2_kernel(const float* __restrict__ rb, const float* __restrict__ rel_bias) {
    int bid = blockIdx.x, t = threadIdx.x;
    if (bid < NTR) {
        __shared__ float tile[32][67];
        int k0 = (bid % (KBIG / 32)) * 32, n0 = (bid / (KBIG / 32)) * 64;
#pragma unroll
        for (int i = 0; i < 2; i++) {
            int idx2 = t + i * 256;
            int row = idx2 >> 4, c4 = idx2 & 15;
            float4 v = *(const float4*)&rb[(size_t)(k0 + row) * D2C + n0 + c4 * 4];
            tile[row][c4 * 4 + 0] = v.x; tile[row][c4 * 4 + 1] = v.y;
            tile[row][c4 * 4 + 2] = v.z; tile[row][c4 * 4 + 3] = v.w;
        }
        __syncthreads();
        int n = t >> 2, kg = t & 3;
        __half hv[8];
#pragma unroll
        for (int j = 0; j < 8; j++) hv[j] = __float2half_rn(tile[kg * 8 + j][n]);
        *(uint4*)&g_WT[(size_t)(n0 + n) * KBIG2 + k0 + kg * 8] = *(uint4*)hv;
        return;
    }
    bid -= NTR;
    int idx2 = bid * 256 + t;
    if (idx2 < 30720) {
        int n = idx2 / 30, j = idx2 % 30;
        g_WT[(size_t)n * KBIG2 + KBIG + j] = __float2half_rn(rel_bias[j * D2C + n]);
    }
}

__device__ __forceinline__ float block_sum(float v, float* red) {
    int t = threadIdx.x;
    red[t] = v; __syncthreads();
#pragma unroll
    for (int s = 128; s > 0; s >>= 1) { if (t < s) red[t] += red[t + s]; __syncthreads(); }
    float r = red[0]; __syncthreads();
    return r;
}

__global__ void ln_mlp_kernel(const float* __restrict__ b0) {
    __shared__ float red[256];
    int b = blockIdx.x, t = threadIdx.x;
    float v[4], s = 0.0f;
#pragma unroll
    for (int u = 0; u < 4; u++) {
        int i = t + u * 256;
        v[u] = g_x0[b * D2C + i] + g_x0[(size_t)(BB + b) * D2C + i] + b0[i];
        s += v[u];
    }
    float mean = block_sum(s, red) * (1.0f / D2C);
    float d = 0.0f;
#pragma unroll
    for (int u = 0; u < 4; u++) { float dv = v[u] - mean; d += dv * dv; }
    float inv = rsqrtf(block_sum(d, red) * (1.0f / D2C) + LN_EPS_F);
#pragma unroll
    for (int u = 0; u < 4; u++)
        g_xstack[(size_t)(BB + b) * D2C + t + u * 256] = __float2half_rn((v[u] - mean) * inv);
}

extern "C" void kernel_launch(void* const* d_in, const int* in_sizes, int n_in,
                              void* d_out, int out_size) {
    const float* ax = (const float*)d_in[0];
    const float* ag = (const float*)d_in[1];
    const int* idx = (const int*)d_in[2];
    const float* rel_base = (const float*)d_in[3];
    const float* rel_att = (const float*)d_in[4];
    const float* rel_bias = (const float*)d_in[5];
    const float* rax = (const float*)d_in[6];
    const float* rag = (const float*)d_in[7];
    const float* W1 = (const float*)d_in[8];
    const float* b1 = (const float*)d_in[9];
    const float* W2 = (const float*)d_in[10];
    const float* b2 = (const float*)d_in[11];
    const float* W0 = (const float*)d_in[12];
    const float* b0 = (const float*)d_in[13];
    const float* Wa1 = (const float*)d_in[14];
    const float* ba1 = (const float*)d_in[15];
    const float* Wa2 = (const float*)d_in[16];
    const float* ba2 = (const float*)d_in[17];
    float* out = (float*)d_out;

    __half *pWT, *peh2, *path, *phin, *ph1, *ph2, *pxs, *pa;
    __half *pw1, *pw2, *pw0, *pwa1, *pwa2;
    float *prt, *px0;
    cudaGetSymbolAddress((void**)&pWT, g_WT);
    cudaGetSymbolAddress((void**)&peh2, g_eh2);
    cudaGetSymbolAddress((void**)&path, g_atth);
    cudaGetSymbolAddress((void**)&phin, g_hin);
    cudaGetSymbolAddress((void**)&ph1, g_h1);
    cudaGetSymbolAddress((void**)&ph2, g_h2);
    cudaGetSymbolAddress((void**)&pxs, g_xstack);
    cudaGetSymbolAddress((void**)&pa, g_a);
    cudaGetSymbolAddress((void**)&prt, g_rt);
    cudaGetSymbolAddress((void**)&px0, g_x0);
    cudaGetSymbolAddress((void**)&pw1, g_w1h);
    cudaGetSymbolAddress((void**)&pw2, g_w2h);
    cudaGetSymbolAddress((void**)&pw0, g_w0h);
    cudaGetSymbolAddress((void**)&pwa1, g_wa1h);
    cudaGetSymbolAddress((void**)&pwa2, g_wa2h);

    const int SMB256 = 4 * (128 + 256) * 40 * 2;  // 122880
    const int SMB128 = 4 * (128 + 128) * 40 * 2;  // 81920
    const int SMB64  = 4 * (64 + 128) * 40 * 2;   // 61440
    const int SMG6   = 4 * 256 * 40 * 2;          // 81920
    cudaFuncSetAttribute(g1_kernel,
                         cudaFuncAttributeMaxDynamicSharedMemorySize, SMB256);
    cudaFuncSetAttribute(hgemm<128, 128, 0, 0>,
                         cudaFuncAttributeMaxDynamicSharedMemorySize, SMB128);
    cudaFuncSetAttribute(hgemm<128, 128, 1, 1>,
                         cudaFuncAttributeMaxDynamicSharedMemorySize, SMB128);
    cudaFuncSetAttribute(hgemm<64, 128, 1, 1>,
                         cudaFuncAttributeMaxDynamicSharedMemorySize, SMB64);
    cudaFuncSetAttribute(g6fuse_kernel,
                         cudaFuncAttributeMaxDynamicSharedMemorySize, SMG6);

    static cudaStream_t s2 = nullptr;
    static cudaEvent_t evFork = nullptr, evJoin = nullptr;
    if (!s2) {
        cudaStreamCreateWithFlags(&s2, cudaStreamNonBlocking);
        cudaEventCreateWithFlags(&evFork, cudaEventDisableTiming);
        cudaEventCreateWithFlags(&evJoin, cudaEventDisableTiming);
    }

    int n1 = HIDC * D2C / 4, n2 = HIDC * HIDC / 4, n3 = D2C * HIDC / 4;
    int n4 = DIMC * D2C / 4, n5 = D2C * DIMC / 4;

    // front1: prep + wa1/wa2 copies (pre-fork; A-side deps)
    front1_kernel<<<NPR + (n4 + n5 + 255) / 256, 256>>>(
        ax, ag, idx, rel_att, rax, rag, Wa1, pwa1, n4, Wa2, pwa2, n5);

    // fork branch B
    cudaEventRecord(evFork, 0);
    cudaStreamWaitEvent(s2, evFork, 0);

    // branch B: weight copies -> G2 -> G3 -> G4 -> ln_mlp -> G5b
    copy3_kernel<<<(n1 + n2 + n3 + 255) / 256, 256, 0, s2>>>(
        W1, pw1, n1, W2, pw2, n2, W0, pw0, n3);
    hgemm<128, 128, 1, 1><<<dim3(HIDC / 128, BB / 128, 1), 512, SMB128, s2>>>(
        phin, pw1, b1, ph1, BB, HIDC, D2C, D2C);
    hgemm<128, 128, 1, 1><<<dim3(HIDC / 128, BB / 128, 1), 512, SMB128, s2>>>(
        ph1, pw2, b2, ph2, BB, HIDC, HIDC, HIDC);
    hgemm<128, 128, 0, 0><<<dim3(D2C / 128, BB / 128, 2), 512, SMB128, s2>>>(
        ph2, pw0, nullptr, px0, BB, D2C, HIDC, HIDC / 2);
    ln_mlp_kernel<<<BB, 256, 0, s2>>>(b0);
    hgemm<64, 128, 1, 1><<<dim3(DIMC / 128, BB / 64, 1), 512, SMB64, s2>>>(
        pxs + (size_t)BB * D2C, pwa1, ba1, pa + (size_t)BB * DIMC, BB, DIMC, D2C, D2C);
    cudaEventRecord(evJoin, s2);

    // branch A (main): front2 (transpose, overlapped with B) -> G1 -> lnr -> G5a
    front2_kernel<<<NTR + NBI, 256>>>(rel_base, rel_bias);
    g1_kernel<<<dim3(D2C / 256, BB / 128, G1Z), 512, SMB256>>>(peh2, pWT, prt, path);
    lnr_kernel<<<BB, 512>>>();
    hgemm<64, 128, 1, 1><<<dim3(DIMC / 128, BB / 64, 1), 512, SMB64>>>(
        pxs, pwa1, ba1, pa, BB, DIMC, D2C, D2C);

    // join, then G6 + fuse
    cudaStreamWaitEvent(0, evJoin, 0);
    g6fuse_kernel<<<dim3(D2C / 128, BB / 64), 512, SMG6>>>(pa, pwa2, ba2, out);
}